// round 1
// baseline (speedup 1.0000x reference)
#include <cuda_runtime.h>
#include <math.h>

#define BATCH 2048
#define NTOT  4096
#define LAT   2048
#define PROJ  256
#define SROW  257   // padded row stride for sim tiles (conflict-free)

// ---------------- device scratch (no runtime allocation allowed) -------------
__device__ float g_X[(size_t)NTOT * LAT];    // 32 MB: projector hidden (then BN+ReLU in place)
__device__ float g_Z[(size_t)NTOT * PROJ];   // 4 MB: projections (then normalized in place)
__device__ float g_sum[2 * LAT];
__device__ float g_sumsq[2 * LAT];
__device__ float g_bna[2 * LAT];
__device__ float g_bnc[2 * LAT];
__device__ float g_S[NTOT];                  // per-row sum of exp(sim-2), j != i
__device__ float g_pos[NTOT];                // sim(i, partner(i))

// ---------------- init: zero the accumulators --------------------------------
__global__ void init_kernel() {
    int i = blockIdx.x * 256 + threadIdx.x;   // grid covers 4096
    if (i < NTOT) g_S[i] = 0.f;
    if (i < 2 * LAT) { g_sum[i] = 0.f; g_sumsq[i] = 0.f; }
}

// ---------------- GEMM1: X = [h_i; h_j] @ W1^T  (M=4096,N=2048,K=2048) -------
// 128x128 tile, BK=16, 256 threads, 8x8 per thread, k-major smem, interleaved
// row mapping (ty + 16*r) => conflict-free LDS broadcast pattern.
__global__ __launch_bounds__(256) void gemm1_kernel(const float* __restrict__ Hi,
                                                    const float* __restrict__ Hj,
                                                    const float* __restrict__ W1) {
    __shared__ float As[16][129];
    __shared__ float Bs[16][129];
    const int t  = threadIdx.x;
    const int tx = t & 15, ty = t >> 4;
    const int m0 = blockIdx.y * 128;
    const int n0 = blockIdx.x * 128;
    const float* Abase = (m0 < BATCH) ? (Hi + (size_t)m0 * LAT)
                                      : (Hj + (size_t)(m0 - BATCH) * LAT);
    const float* Bbase = W1 + (size_t)n0 * LAT;
    const int lrow = t >> 2;          // 0..63
    const int lk4  = (t & 3) * 4;     // 0,4,8,12

    float acc[8][8];
#pragma unroll
    for (int i = 0; i < 8; i++)
#pragma unroll
        for (int j = 0; j < 8; j++) acc[i][j] = 0.f;

    for (int k0 = 0; k0 < LAT; k0 += 16) {
#pragma unroll
        for (int it = 0; it < 2; it++) {
            int row = lrow + it * 64;
            float4 va = *(const float4*)(Abase + (size_t)row * LAT + k0 + lk4);
            As[lk4 + 0][row] = va.x; As[lk4 + 1][row] = va.y;
            As[lk4 + 2][row] = va.z; As[lk4 + 3][row] = va.w;
            float4 vb = *(const float4*)(Bbase + (size_t)row * LAT + k0 + lk4);
            Bs[lk4 + 0][row] = vb.x; Bs[lk4 + 1][row] = vb.y;
            Bs[lk4 + 2][row] = vb.z; Bs[lk4 + 3][row] = vb.w;
        }
        __syncthreads();
#pragma unroll
        for (int k = 0; k < 16; k++) {
            float a[8], b[8];
#pragma unroll
            for (int r = 0; r < 8; r++) a[r] = As[k][ty + 16 * r];
#pragma unroll
            for (int r = 0; r < 8; r++) b[r] = Bs[k][tx + 16 * r];
#pragma unroll
            for (int i = 0; i < 8; i++)
#pragma unroll
                for (int j = 0; j < 8; j++) acc[i][j] = fmaf(a[i], b[j], acc[i][j]);
        }
        __syncthreads();
    }
#pragma unroll
    for (int i = 0; i < 8; i++) {
        int m = m0 + ty + 16 * i;
#pragma unroll
        for (int j = 0; j < 8; j++)
            g_X[(size_t)m * LAT + n0 + tx + 16 * j] = acc[i][j];
    }
}

// ---------------- BN stats: per-column mean/var, two independent groups ------
__global__ void bnstats_kernel() {
    int c  = blockIdx.x * 256 + threadIdx.x;   // column
    int g  = blockIdx.y;                       // group 0 / 1
    int r0 = blockIdx.z * 256;                 // row chunk
    const float* base = g_X + ((size_t)g * BATCH + r0) * LAT + c;
    float s = 0.f, sq = 0.f;
#pragma unroll 4
    for (int r = 0; r < 256; r++) {
        float x = base[(size_t)r * LAT];
        s += x; sq += x * x;
    }
    atomicAdd(&g_sum[g * LAT + c], s);
    atomicAdd(&g_sumsq[g * LAT + c], sq);
}

__global__ void bnfinal_kernel(const float* __restrict__ gamma,
                               const float* __restrict__ beta) {
    int idx = blockIdx.x * 256 + threadIdx.x;  // 0..4095 (g*2048 + c)
    int c = idx & (LAT - 1);
    const float inv = 1.0f / (float)BATCH;
    float mu  = g_sum[idx] * inv;
    float var = g_sumsq[idx] * inv - mu * mu;
    float a = gamma[c] * rsqrtf(var + 1e-5f);
    g_bna[idx] = a;
    g_bnc[idx] = beta[c] - mu * a;
}

// ---------------- fused BN + ReLU (in place over g_X) ------------------------
__global__ void bnrelu_kernel() {
    size_t i = (size_t)blockIdx.x * 256 + threadIdx.x;   // float4 index
    float4* X4 = (float4*)g_X;
    int row = (int)(i >> 9);                   // 512 float4 per row
    int g   = row >> 11;                       // row / 2048
    int c   = ((int)i & 511) * 4;
    const float* A = g_bna + g * LAT;
    const float* C = g_bnc + g * LAT;
    float4 x = X4[i];
    x.x = fmaxf(fmaf(x.x, A[c + 0], C[c + 0]), 0.f);
    x.y = fmaxf(fmaf(x.y, A[c + 1], C[c + 1]), 0.f);
    x.z = fmaxf(fmaf(x.z, A[c + 2], C[c + 2]), 0.f);
    x.w = fmaxf(fmaf(x.w, A[c + 3], C[c + 3]), 0.f);
    X4[i] = x;
}

// ---------------- GEMM2: Z = Xn @ W2^T + b2  (M=4096,N=256,K=2048) -----------
__global__ __launch_bounds__(256) void gemm2_kernel(const float* __restrict__ W2,
                                                    const float* __restrict__ b2) {
    __shared__ float As[16][65];
    __shared__ float Bs[16][65];
    const int t  = threadIdx.x;
    const int tx = t & 15, ty = t >> 4;
    const int m0 = blockIdx.y * 64;
    const int n0 = blockIdx.x * 64;
    const float* Abase = g_X + (size_t)m0 * LAT;
    const float* Bbase = W2 + (size_t)n0 * LAT;
    const int lrow = t >> 2;          // 0..63
    const int lk4  = (t & 3) * 4;

    float acc[4][4];
#pragma unroll
    for (int i = 0; i < 4; i++)
#pragma unroll
        for (int j = 0; j < 4; j++) acc[i][j] = 0.f;

    for (int k0 = 0; k0 < LAT; k0 += 16) {
        float4 va = *(const float4*)(Abase + (size_t)lrow * LAT + k0 + lk4);
        As[lk4 + 0][lrow] = va.x; As[lk4 + 1][lrow] = va.y;
        As[lk4 + 2][lrow] = va.z; As[lk4 + 3][lrow] = va.w;
        float4 vb = *(const float4*)(Bbase + (size_t)lrow * LAT + k0 + lk4);
        Bs[lk4 + 0][lrow] = vb.x; Bs[lk4 + 1][lrow] = vb.y;
        Bs[lk4 + 2][lrow] = vb.z; Bs[lk4 + 3][lrow] = vb.w;
        __syncthreads();
#pragma unroll
        for (int k = 0; k < 16; k++) {
            float a[4], b[4];
#pragma unroll
            for (int r = 0; r < 4; r++) a[r] = As[k][ty + 16 * r];
#pragma unroll
            for (int r = 0; r < 4; r++) b[r] = Bs[k][tx + 16 * r];
#pragma unroll
            for (int i = 0; i < 4; i++)
#pragma unroll
                for (int j = 0; j < 4; j++) acc[i][j] = fmaf(a[i], b[j], acc[i][j]);
        }
        __syncthreads();
    }
#pragma unroll
    for (int i = 0; i < 4; i++) {
        int m = m0 + ty + 16 * i;
#pragma unroll
        for (int j = 0; j < 4; j++) {
            int p = n0 + tx + 16 * j;
            g_Z[(size_t)m * PROJ + p] = acc[i][j] + b2[p];
        }
    }
}

// ---------------- row-normalize Z in place, fold in sqrt(1/TEMP) -------------
__global__ void rownorm_kernel() {
    int row  = blockIdx.x * 8 + (threadIdx.x >> 5);   // one warp per row
    int lane = threadIdx.x & 31;
    float4* zr = (float4*)(g_Z + (size_t)row * PROJ); // 64 float4 per row
    float4 v0 = zr[lane];
    float4 v1 = zr[lane + 32];
    float ss = v0.x * v0.x + v0.y * v0.y + v0.z * v0.z + v0.w * v0.w
             + v1.x * v1.x + v1.y * v1.y + v1.z * v1.z + v1.w * v1.w;
#pragma unroll
    for (int off = 16; off; off >>= 1) ss += __shfl_xor_sync(0xffffffffu, ss, off);
    float s = 1.41421356237f / fmaxf(sqrtf(ss), 1e-8f);  // sqrt(1/TEMP)/max(||z||,eps)
    v0.x *= s; v0.y *= s; v0.z *= s; v0.w *= s;
    v1.x *= s; v1.y *= s; v1.z *= s; v1.w *= s;
    zr[lane] = v0;
    zr[lane + 32] = v1;
}

// ---------------- sim tile + online exp-sum (never materializes sim) ---------
// 64x64 tile per block, 256 threads, 4x4 per thread, K=256.
// sim(i,j) = zn_i . zn_j  (TEMP folded into zn).  LSE shift fixed at 2.0
// (cos/TEMP <= 2), so exp(d-2) in [e^-4, 1] -- always safe.
__global__ __launch_bounds__(256) void sim_kernel() {
    extern __shared__ float sh[];
    float* sI = sh;                 // [64][SROW]
    float* sJ = sh + 64 * SROW;     // [64][SROW]
    const int t  = threadIdx.x;
    const int tx = t & 15, ty = t >> 4;
    const int i0 = blockIdx.y * 64, j0 = blockIdx.x * 64;

#pragma unroll
    for (int it = 0; it < 16; it++) {
        int id  = t + it * 256;        // 0..4095
        int row = id >> 6;             // 64 float4 per row
        int c4  = id & 63;
        float4 v = *(const float4*)(g_Z + (size_t)(i0 + row) * PROJ + c4 * 4);
        float* p = sI + row * SROW + c4 * 4;
        p[0] = v.x; p[1] = v.y; p[2] = v.z; p[3] = v.w;
        float4 w = *(const float4*)(g_Z + (size_t)(j0 + row) * PROJ + c4 * 4);
        float* q = sJ + row * SROW + c4 * 4;
        q[0] = w.x; q[1] = w.y; q[2] = w.z; q[3] = w.w;
    }
    __syncthreads();

    float acc[4][4];
#pragma unroll
    for (int i = 0; i < 4; i++)
#pragma unroll
        for (int j = 0; j < 4; j++) acc[i][j] = 0.f;

#pragma unroll 8
    for (int k = 0; k < PROJ; k++) {
        float a[4], b[4];
#pragma unroll
        for (int r = 0; r < 4; r++) a[r] = sI[(ty + 16 * r) * SROW + k];
#pragma unroll
        for (int r = 0; r < 4; r++) b[r] = sJ[(tx + 16 * r) * SROW + k];
#pragma unroll
        for (int i = 0; i < 4; i++)
#pragma unroll
            for (int j = 0; j < 4; j++) acc[i][j] = fmaf(a[i], b[j], acc[i][j]);
    }

#pragma unroll
    for (int ri = 0; ri < 4; ri++) {
        int i = i0 + ty + 16 * ri;
        int partner = (i < BATCH) ? i + BATCH : i - BATCH;
        float rowsum = 0.f;
#pragma unroll
        for (int rj = 0; rj < 4; rj++) {
            int j = j0 + tx + 16 * rj;
            float d = acc[ri][rj];
            if (j == partner) g_pos[i] = d;          // exactly one writer globally
            if (j != i) rowsum += expf(d - 2.0f);    // positive IS in the denominator
        }
        // reduce across the 16 tx lanes (xor widths stay inside each 16-group)
#pragma unroll
        for (int off = 8; off; off >>= 1)
            rowsum += __shfl_xor_sync(0xffffffffu, rowsum, off);
        if (tx == 0) atomicAdd(&g_S[i], rowsum);
    }
}

// ---------------- final reduction: loss = mean(2 + log S_i - pos_i) ----------
__global__ void loss_kernel(float* __restrict__ out) {
    __shared__ float red[256];
    int t = threadIdx.x;
    float s = 0.f;
    for (int i = t; i < NTOT; i += 256)
        s += 2.0f + logf(g_S[i]) - g_pos[i];
    red[t] = s;
    __syncthreads();
    for (int off = 128; off; off >>= 1) {
        if (t < off) red[t] += red[t + off];
        __syncthreads();
    }
    if (t == 0) out[0] = red[0] / (float)NTOT;
}

// ---------------- launch ------------------------------------------------------
extern "C" void kernel_launch(void* const* d_in, const int* in_sizes, int n_in,
                              void* d_out, int out_size) {
    const float* h_i   = (const float*)d_in[0];
    const float* h_j   = (const float*)d_in[1];
    const float* W1    = (const float*)d_in[2];
    const float* gamma = (const float*)d_in[3];
    const float* beta  = (const float*)d_in[4];
    const float* W2    = (const float*)d_in[5];
    const float* b2    = (const float*)d_in[6];
    float* out = (float*)d_out;

    // 131,584 B dynamic smem for sim_kernel (idempotent; capture-safe host call)
    cudaFuncSetAttribute(sim_kernel, cudaFuncAttributeMaxDynamicSharedMemorySize,
                         2 * 64 * SROW * 4);

    init_kernel<<<16, 256>>>();
    gemm1_kernel<<<dim3(16, 32), 256>>>(h_i, h_j, W1);
    bnstats_kernel<<<dim3(8, 2, 8), 256>>>();
    bnfinal_kernel<<<16, 256>>>(gamma, beta);
    bnrelu_kernel<<<8192, 256>>>();
    gemm2_kernel<<<dim3(4, 64), 256>>>(W2, b2);
    rownorm_kernel<<<512, 256>>>();
    sim_kernel<<<dim3(64, 64), 256, 2 * 64 * SROW * 4>>>();
    loss_kernel<<<1, 256>>>(out);
}

// round 3
// speedup vs baseline: 2.2179x; 2.2179x over previous
#include <cuda_runtime.h>
#include <cuda_bf16.h>
#include <math.h>
#include <stdint.h>

#define BATCH 2048
#define NTOT  4096
#define LAT   2048
#define PROJ  256
#define KSPL  6144      // split-bf16 concatenated K = 3*2048
#define SROW  257       // padded row stride for SIMT sim tiles
#define NC    (KSPL / 64)   // 96 k-chunks of 64

// ---------------- device scratch (no runtime allocation allowed) -------------
__device__ __nv_bfloat16 g_A2[(size_t)NTOT * KSPL];   // [Hh | Hl | Hh]
__device__ __nv_bfloat16 g_B1s[(size_t)LAT * KSPL];   // [W1h | W1h | W1l]
__device__ __nv_bfloat16 g_W2s[(size_t)PROJ * KSPL];  // [W2h | W2h | W2l]
__device__ __nv_bfloat16 g_X2[(size_t)NTOT * KSPL];   // [Xh | Xl | Xh]
__device__ float g_X[(size_t)NTOT * LAT];
__device__ float g_Z[(size_t)NTOT * PROJ];
__device__ float g_sum[2 * LAT];
__device__ float g_sumsq[2 * LAT];
__device__ float g_bna[2 * LAT];
__device__ float g_bnc[2 * LAT];
__device__ float g_S[NTOT];
__device__ float g_pos[NTOT];

// ---------------- PTX helpers (all baseline ISA, no sm_103a-only ops) --------
__device__ __forceinline__ uint32_t smem_u32(const void* p) {
    return (uint32_t)__cvta_generic_to_shared(p);
}
__device__ __forceinline__ void cp16(uint32_t dst, const void* src) {
    asm volatile("cp.async.cg.shared.global [%0], [%1], 16;" :: "r"(dst), "l"(src));
}
__device__ __forceinline__ void cp_commit() { asm volatile("cp.async.commit_group;"); }
__device__ __forceinline__ void cp_wait1()  { asm volatile("cp.async.wait_group 1;"); }
__device__ __forceinline__ void cp_wait0()  { asm volatile("cp.async.wait_group 0;"); }
__device__ __forceinline__ void ldsm_x4(uint32_t a, uint32_t& r0, uint32_t& r1,
                                        uint32_t& r2, uint32_t& r3) {
    asm volatile("ldmatrix.sync.aligned.m8n8.x4.shared.b16 {%0,%1,%2,%3}, [%4];"
                 : "=r"(r0), "=r"(r1), "=r"(r2), "=r"(r3) : "r"(a));
}
__device__ __forceinline__ void mma16816(float* c, const uint32_t* a, const uint32_t* b) {
    asm volatile("mma.sync.aligned.m16n8k16.row.col.f32.bf16.bf16.f32 "
                 "{%0,%1,%2,%3}, {%4,%5,%6,%7}, {%8,%9}, {%0,%1,%2,%3};"
                 : "+f"(c[0]), "+f"(c[1]), "+f"(c[2]), "+f"(c[3])
                 : "r"(a[0]), "r"(a[1]), "r"(a[2]), "r"(a[3]), "r"(b[0]), "r"(b[1]));
}

// ---------------- init --------------------------------------------------------
__global__ void init_kernel() {
    int i = blockIdx.x * 256 + threadIdx.x;
    if (i < NTOT) g_S[i] = 0.f;
    if (i < 2 * LAT) { g_sum[i] = 0.f; g_sumsq[i] = 0.f; }
}

// ---------------- split fp32 -> concatenated split-bf16 ----------------------
// modeA: [hi | lo | hi]   modeB: [hi | hi | lo]
__device__ __forceinline__ void split_row_pair(const float2 v, __nv_bfloat162* drow,
                                               int c2, int modeA) {
    __nv_bfloat16 hx = __float2bfloat16(v.x), hy = __float2bfloat16(v.y);
    __nv_bfloat16 lx = __float2bfloat16(v.x - __bfloat162float(hx));
    __nv_bfloat16 ly = __float2bfloat16(v.y - __bfloat162float(hy));
    __nv_bfloat162 hi2; hi2.x = hx; hi2.y = hy;
    __nv_bfloat162 lo2; lo2.x = lx; lo2.y = ly;
    drow[c2] = hi2;
    if (modeA) { drow[1024 + c2] = lo2; drow[2048 + c2] = hi2; }
    else       { drow[1024 + c2] = hi2; drow[2048 + c2] = lo2; }
}

__global__ void splitA_kernel(const float* __restrict__ hi_,
                              const float* __restrict__ hj_) {
    size_t i = (size_t)blockIdx.x * 256 + threadIdx.x;   // pair idx, NTOT*1024
    int row = (int)(i >> 10);
    int c2  = (int)i & 1023;
    float2 v = (row < BATCH) ? ((const float2*)hi_)[i]
                             : ((const float2*)hj_)[i - (size_t)BATCH * 1024];
    split_row_pair(v, (__nv_bfloat162*)(g_A2 + (size_t)row * KSPL), c2, 1);
}

__global__ void splitW_kernel(const float* __restrict__ W1,
                              const float* __restrict__ W2) {
    size_t i = (size_t)blockIdx.x * 256 + threadIdx.x;   // (LAT+PROJ)*1024
    int row = (int)(i >> 10);
    int c2  = (int)i & 1023;
    if (row < LAT) {
        float2 v = ((const float2*)W1)[i];
        split_row_pair(v, (__nv_bfloat162*)(g_B1s + (size_t)row * KSPL), c2, 0);
    } else {
        float2 v = ((const float2*)W2)[i - (size_t)LAT * 1024];
        split_row_pair(v, (__nv_bfloat162*)(g_W2s + (size_t)(row - LAT) * KSPL), c2, 0);
    }
}

// ---------------- mma.sync GEMM core: out[M,N] = A[M,K] * B[N,K]^T -----------
// CTA tile 128x128, BK=64 bf16 (128B rows, SW128 xor swizzle), 256 threads,
// 8 warps (2m x 4n), warp tile 64x32, cp.async double buffering.
// smem: 2 buffers x (A 16KB + B 16KB) = 64 KB dynamic.
__device__ __forceinline__ void gemm_mma_core(const __nv_bfloat16* __restrict__ A,
                                              const __nv_bfloat16* __restrict__ B,
                                              float* __restrict__ out, int ldo,
                                              const float* __restrict__ bias) {
    extern __shared__ char smem[];
    const uint32_t sb = smem_u32(smem);
    const int tid  = threadIdx.x;
    const int lane = tid & 31;
    const int w    = tid >> 5;
    const int wm   = w & 1;        // 0..1  (64-row slab)
    const int wn   = w >> 1;       // 0..3  (32-col slab)
    const int m0 = blockIdx.y * 128;
    const int n0 = blockIdx.x * 128;

    // gmem->smem tile loader: 128 rows x 8 chunks(16B) each for A and B
    auto load_tile = [&](int c, int buf) {
        const uint32_t sA = sb + buf * 32768;
        const uint32_t sB = sA + 16384;
        const int k0 = c * 64;
#pragma unroll
        for (int i = 0; i < 4; i++) {
            int idx = i * 256 + tid;          // 0..1023
            int row = idx >> 3, ch = idx & 7;
            uint32_t dst = (uint32_t)row * 128 + (uint32_t)((ch ^ (row & 7)) * 16);
            cp16(sA + dst, A + (size_t)(m0 + row) * KSPL + k0 + ch * 8);
            cp16(sB + dst, B + (size_t)(n0 + row) * KSPL + k0 + ch * 8);
        }
        cp_commit();
    };

    float acc[4][4][4];
#pragma unroll
    for (int i = 0; i < 4; i++)
#pragma unroll
        for (int j = 0; j < 4; j++)
#pragma unroll
            for (int q = 0; q < 4; q++) acc[i][j][q] = 0.f;

    // per-lane fragment address components (SW128 swizzle, row&7 == lane&7)
    const int rA   = wm * 64 + (lane & 15);        // + mi*16
    const int khA  = lane >> 4;                    // A k-half select
    const int rB   = wn * 32 + ((lane >> 4) << 3) + (lane & 7);   // + np*16
    const int khB  = (lane >> 3) & 1;              // B k-half select
    const int rlow = lane & 7;

    load_tile(0, 0);
    load_tile(1, 1);

    for (int c = 0; c < NC; c++) {
        if (c < NC - 1) cp_wait1(); else cp_wait0();
        __syncthreads();
        const uint32_t sA = sb + (c & 1) * 32768;
        const uint32_t sB = sA + 16384;
#pragma unroll
        for (int ks = 0; ks < 4; ks++) {
            uint32_t af[4][4], bf[4][2];
#pragma unroll
            for (int mi = 0; mi < 4; mi++) {
                uint32_t a = sA + (uint32_t)(rA + mi * 16) * 128
                           + (uint32_t)((((ks * 2) + khA) ^ rlow) * 16);
                ldsm_x4(a, af[mi][0], af[mi][1], af[mi][2], af[mi][3]);
            }
#pragma unroll
            for (int np = 0; np < 2; np++) {
                uint32_t r0, r1, r2, r3;
                uint32_t a = sB + (uint32_t)(rB + np * 16) * 128
                           + (uint32_t)((((ks * 2) + khB) ^ rlow) * 16);
                ldsm_x4(a, r0, r1, r2, r3);
                bf[np * 2 + 0][0] = r0; bf[np * 2 + 0][1] = r1;
                bf[np * 2 + 1][0] = r2; bf[np * 2 + 1][1] = r3;
            }
#pragma unroll
            for (int mi = 0; mi < 4; mi++)
#pragma unroll
                for (int nf = 0; nf < 4; nf++)
                    mma16816(acc[mi][nf], af[mi], bf[nf]);
        }
        __syncthreads();
        if (c + 2 < NC) load_tile(c + 2, c & 1);
    }

    // epilogue
#pragma unroll
    for (int mi = 0; mi < 4; mi++) {
        int row = m0 + wm * 64 + mi * 16 + (lane >> 2);
#pragma unroll
        for (int nf = 0; nf < 4; nf++) {
            int col = n0 + wn * 32 + nf * 8 + (lane & 3) * 2;
            float2 v0 = make_float2(acc[mi][nf][0], acc[mi][nf][1]);
            float2 v1 = make_float2(acc[mi][nf][2], acc[mi][nf][3]);
            if (bias) {
                v0.x += bias[col]; v0.y += bias[col + 1];
                v1.x += bias[col]; v1.y += bias[col + 1];
            }
            *(float2*)(out + (size_t)row * ldo + col) = v0;
            *(float2*)(out + (size_t)(row + 8) * ldo + col) = v1;
        }
    }
}

__global__ __launch_bounds__(256) void gemm1_mma_kernel() {
    gemm_mma_core(g_A2, g_B1s, g_X, LAT, nullptr);
}
__global__ __launch_bounds__(256) void gemm2_mma_kernel(const float* __restrict__ b2) {
    gemm_mma_core(g_X2, g_W2s, g_Z, PROJ, b2);
}

// ---------------- BN stats ----------------------------------------------------
__global__ void bnstats_kernel() {
    int c  = blockIdx.x * 256 + threadIdx.x;
    int g  = blockIdx.y;
    int r0 = blockIdx.z * 256;
    const float* base = g_X + ((size_t)g * BATCH + r0) * LAT + c;
    float s = 0.f, sq = 0.f;
#pragma unroll 4
    for (int r = 0; r < 256; r++) {
        float x = base[(size_t)r * LAT];
        s += x; sq += x * x;
    }
    atomicAdd(&g_sum[g * LAT + c], s);
    atomicAdd(&g_sumsq[g * LAT + c], sq);
}

__global__ void bnfinal_kernel(const float* __restrict__ gamma,
                               const float* __restrict__ beta) {
    int idx = blockIdx.x * 256 + threadIdx.x;
    int c = idx & (LAT - 1);
    const float inv = 1.0f / (float)BATCH;
    float mu  = g_sum[idx] * inv;
    float var = g_sumsq[idx] * inv - mu * mu;
    float a = gamma[c] * rsqrtf(var + 1e-5f);
    g_bna[idx] = a;
    g_bnc[idx] = beta[c] - mu * a;
}

// ---------------- fused BN + ReLU + split-bf16 emit --------------------------
__global__ void bnrelu_split_kernel() {
    size_t i = (size_t)blockIdx.x * 256 + threadIdx.x;   // pair idx, NTOT*1024
    int row = (int)(i >> 10);
    int g   = row >> 11;
    int c2  = (int)i & 1023;
    const float* Ac = g_bna + g * LAT;
    const float* Cc = g_bnc + g * LAT;
    float2 x = ((const float2*)g_X)[i];
    float2 y;
    y.x = fmaxf(fmaf(x.x, Ac[2 * c2 + 0], Cc[2 * c2 + 0]), 0.f);
    y.y = fmaxf(fmaf(x.y, Ac[2 * c2 + 1], Cc[2 * c2 + 1]), 0.f);
    split_row_pair(y, (__nv_bfloat162*)(g_X2 + (size_t)row * KSPL), c2, 1);
}

// ---------------- row-normalize Z in place (folds sqrt(1/TEMP)) --------------
__global__ void rownorm_kernel() {
    int row  = blockIdx.x * 8 + (threadIdx.x >> 5);
    int lane = threadIdx.x & 31;
    float4* zr = (float4*)(g_Z + (size_t)row * PROJ);
    float4 v0 = zr[lane];
    float4 v1 = zr[lane + 32];
    float ss = v0.x * v0.x + v0.y * v0.y + v0.z * v0.z + v0.w * v0.w
             + v1.x * v1.x + v1.y * v1.y + v1.z * v1.z + v1.w * v1.w;
#pragma unroll
    for (int off = 16; off; off >>= 1) ss += __shfl_xor_sync(0xffffffffu, ss, off);
    float s = 1.41421356237f / fmaxf(sqrtf(ss), 1e-8f);
    v0.x *= s; v0.y *= s; v0.z *= s; v0.w *= s;
    v1.x *= s; v1.y *= s; v1.z *= s; v1.w *= s;
    zr[lane] = v0;
    zr[lane + 32] = v1;
}

// ---------------- SIMT sim tile + online exp-sum -----------------------------
__global__ __launch_bounds__(256) void sim_kernel() {
    extern __shared__ float sh[];
    float* sI = sh;
    float* sJ = sh + 64 * SROW;
    const int t  = threadIdx.x;
    const int tx = t & 15, ty = t >> 4;
    const int i0 = blockIdx.y * 64, j0 = blockIdx.x * 64;

#pragma unroll
    for (int it = 0; it < 16; it++) {
        int id  = t + it * 256;
        int row = id >> 6;
        int c4  = id & 63;
        float4 v = *(const float4*)(g_Z + (size_t)(i0 + row) * PROJ + c4 * 4);
        float* p = sI + row * SROW + c4 * 4;
        p[0] = v.x; p[1] = v.y; p[2] = v.z; p[3] = v.w;
        float4 w = *(const float4*)(g_Z + (size_t)(j0 + row) * PROJ + c4 * 4);
        float* q = sJ + row * SROW + c4 * 4;
        q[0] = w.x; q[1] = w.y; q[2] = w.z; q[3] = w.w;
    }
    __syncthreads();

    float acc[4][4];
#pragma unroll
    for (int i = 0; i < 4; i++)
#pragma unroll
        for (int j = 0; j < 4; j++) acc[i][j] = 0.f;

#pragma unroll 8
    for (int k = 0; k < PROJ; k++) {
        float a[4], b[4];
#pragma unroll
        for (int r = 0; r < 4; r++) a[r] = sI[(ty + 16 * r) * SROW + k];
#pragma unroll
        for (int r = 0; r < 4; r++) b[r] = sJ[(tx + 16 * r) * SROW + k];
#pragma unroll
        for (int i = 0; i < 4; i++)
#pragma unroll
            for (int j = 0; j < 4; j++) acc[i][j] = fmaf(a[i], b[j], acc[i][j]);
    }

#pragma unroll
    for (int ri = 0; ri < 4; ri++) {
        int i = i0 + ty + 16 * ri;
        int partner = (i < BATCH) ? i + BATCH : i - BATCH;
        float rowsum = 0.f;
#pragma unroll
        for (int rj = 0; rj < 4; rj++) {
            int j = j0 + tx + 16 * rj;
            float d = acc[ri][rj];
            if (j == partner) g_pos[i] = d;
            if (j != i) rowsum += expf(d - 2.0f);
        }
#pragma unroll
        for (int off = 8; off; off >>= 1)
            rowsum += __shfl_xor_sync(0xffffffffu, rowsum, off);
        if (tx == 0) atomicAdd(&g_S[i], rowsum);
    }
}

// ---------------- final reduction --------------------------------------------
__global__ void loss_kernel(float* __restrict__ out) {
    __shared__ float red[256];
    int t = threadIdx.x;
    float s = 0.f;
    for (int i = t; i < NTOT; i += 256)
        s += 2.0f + logf(g_S[i]) - g_pos[i];
    red[t] = s;
    __syncthreads();
    for (int off = 128; off; off >>= 1) {
        if (t < off) red[t] += red[t + off];
        __syncthreads();
    }
    if (t == 0) out[0] = red[0] / (float)NTOT;
}

// ---------------- launch ------------------------------------------------------
extern "C" void kernel_launch(void* const* d_in, const int* in_sizes, int n_in,
                              void* d_out, int out_size) {
    const float* h_i   = (const float*)d_in[0];
    const float* h_j   = (const float*)d_in[1];
    const float* W1    = (const float*)d_in[2];
    const float* gamma = (const float*)d_in[3];
    const float* beta  = (const float*)d_in[4];
    const float* W2    = (const float*)d_in[5];
    const float* b2    = (const float*)d_in[6];
    float* out = (float*)d_out;

    const int GEMM_SMEM = 65536;
    cudaFuncSetAttribute(gemm1_mma_kernel, cudaFuncAttributeMaxDynamicSharedMemorySize, GEMM_SMEM);
    cudaFuncSetAttribute(gemm2_mma_kernel, cudaFuncAttributeMaxDynamicSharedMemorySize, GEMM_SMEM);
    cudaFuncSetAttribute(sim_kernel, cudaFuncAttributeMaxDynamicSharedMemorySize, 2 * 64 * SROW * 4);

    init_kernel<<<16, 256>>>();
    splitA_kernel<<<NTOT * 1024 / 256, 256>>>(h_i, h_j);
    splitW_kernel<<<(LAT + PROJ) * 1024 / 256, 256>>>(W1, W2);
    gemm1_mma_kernel<<<dim3(16, 32), 256, GEMM_SMEM>>>();
    bnstats_kernel<<<dim3(8, 2, 8), 256>>>();
    bnfinal_kernel<<<16, 256>>>(gamma, beta);
    bnrelu_split_kernel<<<NTOT * 1024 / 256, 256>>>();
    gemm2_mma_kernel<<<dim3(2, 32), 256, GEMM_SMEM>>>(b2);
    rownorm_kernel<<<512, 256>>>();
    sim_kernel<<<dim3(64, 64), 256, 2 * 64 * SROW * 4>>>();
    loss_kernel<<<1, 256>>>(out);
}

// round 4
// speedup vs baseline: 3.7230x; 1.6786x over previous
#include <cuda_runtime.h>
#include <cuda_bf16.h>
#include <math.h>
#include <stdint.h>

#define BATCH 2048
#define NTOT  4096
#define LAT   2048
#define PROJ  256
#define KSPL  6144          // split-bf16 concatenated K for GEMM1/2
#define KZ    768           // split-bf16 concatenated K for sim (3*256)
#define NC1   (KSPL / 64)   // 96
#define NCZ   (KZ / 64)     // 12

// ---------------- device scratch (no runtime allocation allowed) -------------
__device__ __nv_bfloat16 g_A2[(size_t)NTOT * KSPL];   // [Hh | Hl | Hh]
__device__ __nv_bfloat16 g_B1s[(size_t)LAT * KSPL];   // [W1h | W1h | W1l]
__device__ __nv_bfloat16 g_W2s[(size_t)PROJ * KSPL];  // [W2h | W2h | W2l]
__device__ __nv_bfloat16 g_X2[(size_t)NTOT * KSPL];   // [Xh | Xl | Xh]
__device__ __nv_bfloat16 g_ZsA[(size_t)NTOT * KZ];    // normalized Z, [h|l|h]
__device__ __nv_bfloat16 g_ZsB[(size_t)NTOT * KZ];    // normalized Z, [h|h|l]
__device__ float g_X[(size_t)NTOT * LAT];
__device__ float g_Zp[(size_t)2 * NTOT * PROJ];       // split-K partial outputs
__device__ float g_sum[2 * LAT];
__device__ float g_sumsq[2 * LAT];
__device__ float g_bna[2 * LAT];
__device__ float g_bnc[2 * LAT];
__device__ float g_S[NTOT];
__device__ float g_pos[NTOT];

// ---------------- PTX helpers (baseline ISA only) ----------------------------
__device__ __forceinline__ uint32_t smem_u32(const void* p) {
    return (uint32_t)__cvta_generic_to_shared(p);
}
__device__ __forceinline__ void cp16(uint32_t dst, const void* src) {
    asm volatile("cp.async.cg.shared.global [%0], [%1], 16;" :: "r"(dst), "l"(src));
}
__device__ __forceinline__ void cp_commit() { asm volatile("cp.async.commit_group;"); }
__device__ __forceinline__ void cp_wait1()  { asm volatile("cp.async.wait_group 1;"); }
__device__ __forceinline__ void cp_wait0()  { asm volatile("cp.async.wait_group 0;"); }
__device__ __forceinline__ void ldsm_x4(uint32_t a, uint32_t& r0, uint32_t& r1,
                                        uint32_t& r2, uint32_t& r3) {
    asm volatile("ldmatrix.sync.aligned.m8n8.x4.shared.b16 {%0,%1,%2,%3}, [%4];"
                 : "=r"(r0), "=r"(r1), "=r"(r2), "=r"(r3) : "r"(a));
}
__device__ __forceinline__ void mma16816(float* c, const uint32_t* a, const uint32_t* b) {
    asm volatile("mma.sync.aligned.m16n8k16.row.col.f32.bf16.bf16.f32 "
                 "{%0,%1,%2,%3}, {%4,%5,%6,%7}, {%8,%9}, {%0,%1,%2,%3};"
                 : "+f"(c[0]), "+f"(c[1]), "+f"(c[2]), "+f"(c[3])
                 : "r"(a[0]), "r"(a[1]), "r"(a[2]), "r"(a[3]), "r"(b[0]), "r"(b[1]));
}

// FMA-only exp for y in ~[-4.1, 0.1]  (avoids MUFU.EX2 throughput wall)
__device__ __forceinline__ float fexp(float y) {
    float t = y * 1.4426950408889634f;
    float n = rintf(t);
    float f = t - n;
    float p =              1.5403530e-4f;
    p = fmaf(p, f, 1.3333558e-3f);
    p = fmaf(p, f, 9.6181291e-3f);
    p = fmaf(p, f, 5.5504109e-2f);
    p = fmaf(p, f, 2.4022651e-1f);
    p = fmaf(p, f, 6.9314718e-1f);
    p = fmaf(p, f, 1.0f);
    int e = ((int)n + 127) << 23;
    return p * __int_as_float(e);
}

// ---------------- init --------------------------------------------------------
__global__ void init_kernel() {
    int i = blockIdx.x * 256 + threadIdx.x;
    if (i < NTOT) g_S[i] = 0.f;
    if (i < 2 * LAT) { g_sum[i] = 0.f; g_sumsq[i] = 0.f; }
}

// ---------------- split fp32 -> concatenated split-bf16 ----------------------
// modeA: [hi | lo | hi]   modeB: [hi | hi | lo]
__device__ __forceinline__ void split_row_pair(const float2 v, __nv_bfloat162* drow,
                                               int c2, int modeA) {
    __nv_bfloat16 hx = __float2bfloat16(v.x), hy = __float2bfloat16(v.y);
    __nv_bfloat16 lx = __float2bfloat16(v.x - __bfloat162float(hx));
    __nv_bfloat16 ly = __float2bfloat16(v.y - __bfloat162float(hy));
    __nv_bfloat162 hi2; hi2.x = hx; hi2.y = hy;
    __nv_bfloat162 lo2; lo2.x = lx; lo2.y = ly;
    drow[c2] = hi2;
    if (modeA) { drow[1024 + c2] = lo2; drow[2048 + c2] = hi2; }
    else       { drow[1024 + c2] = hi2; drow[2048 + c2] = lo2; }
}

__global__ void splitA_kernel(const float* __restrict__ hi_,
                              const float* __restrict__ hj_) {
    size_t i = (size_t)blockIdx.x * 256 + threadIdx.x;
    int row = (int)(i >> 10);
    int c2  = (int)i & 1023;
    float2 v = (row < BATCH) ? ((const float2*)hi_)[i]
                             : ((const float2*)hj_)[i - (size_t)BATCH * 1024];
    split_row_pair(v, (__nv_bfloat162*)(g_A2 + (size_t)row * KSPL), c2, 1);
}

__global__ void splitW_kernel(const float* __restrict__ W1,
                              const float* __restrict__ W2) {
    size_t i = (size_t)blockIdx.x * 256 + threadIdx.x;
    int row = (int)(i >> 10);
    int c2  = (int)i & 1023;
    if (row < LAT) {
        float2 v = ((const float2*)W1)[i];
        split_row_pair(v, (__nv_bfloat162*)(g_B1s + (size_t)row * KSPL), c2, 0);
    } else {
        float2 v = ((const float2*)W2)[i - (size_t)LAT * 1024];
        split_row_pair(v, (__nv_bfloat162*)(g_W2s + (size_t)(row - LAT) * KSPL), c2, 0);
    }
}

// ---------------- shared MMA mainloop (3-stage cp.async pipeline) ------------
// CTA tile 128x128, BK=64 bf16 (128B rows, xor swizzle), 256 threads,
// 8 warps (2m x 4n), warp tile 64x32. smem: 3 x 32KB = 96KB.
template <int KS>
__device__ __forceinline__ void mma_mainloop(const __nv_bfloat16* __restrict__ A,
                                             const __nv_bfloat16* __restrict__ B,
                                             int m0, int n0, int nck,
                                             float acc[4][4][4]) {
    extern __shared__ char smem[];
    const uint32_t sb = smem_u32(smem);
    const int tid  = threadIdx.x;
    const int lane = tid & 31;
    const int w    = tid >> 5;
    const int wm   = w & 1;
    const int wn   = w >> 1;

    auto load_tile = [&](int c) {
        const uint32_t sA = sb + (uint32_t)(c % 3) * 32768u;
        const uint32_t sB = sA + 16384u;
        const int k0 = c * 64;
#pragma unroll
        for (int i = 0; i < 4; i++) {
            int idx = i * 256 + tid;
            int row = idx >> 3, ch = idx & 7;
            uint32_t dst = (uint32_t)row * 128 + (uint32_t)((ch ^ (row & 7)) * 16);
            cp16(sA + dst, A + (size_t)(m0 + row) * KS + k0 + ch * 8);
            cp16(sB + dst, B + (size_t)(n0 + row) * KS + k0 + ch * 8);
        }
        cp_commit();
    };

#pragma unroll
    for (int i = 0; i < 4; i++)
#pragma unroll
        for (int j = 0; j < 4; j++)
#pragma unroll
            for (int q = 0; q < 4; q++) acc[i][j][q] = 0.f;

    const int rA   = wm * 64 + (lane & 15);
    const int khA  = lane >> 4;
    const int rB   = wn * 32 + ((lane >> 4) << 3) + (lane & 7);
    const int khB  = (lane >> 3) & 1;
    const int rlow = lane & 7;

    load_tile(0);
    load_tile(1);

    for (int c = 0; c < nck; c++) {
        if (c < nck - 1) cp_wait1(); else cp_wait0();
        __syncthreads();
        if (c + 2 < nck) load_tile(c + 2);   // overlaps compute of tile c
        const uint32_t sA = sb + (uint32_t)(c % 3) * 32768u;
        const uint32_t sB = sA + 16384u;
#pragma unroll
        for (int ks = 0; ks < 4; ks++) {
            uint32_t af[4][4], bf[4][2];
#pragma unroll
            for (int mi = 0; mi < 4; mi++) {
                uint32_t a = sA + (uint32_t)(rA + mi * 16) * 128
                           + (uint32_t)((((ks * 2) + khA) ^ rlow) * 16);
                ldsm_x4(a, af[mi][0], af[mi][1], af[mi][2], af[mi][3]);
            }
#pragma unroll
            for (int np = 0; np < 2; np++) {
                uint32_t r0, r1, r2, r3;
                uint32_t a = sB + (uint32_t)(rB + np * 16) * 128
                           + (uint32_t)((((ks * 2) + khB) ^ rlow) * 16);
                ldsm_x4(a, r0, r1, r2, r3);
                bf[np * 2 + 0][0] = r0; bf[np * 2 + 0][1] = r1;
                bf[np * 2 + 1][0] = r2; bf[np * 2 + 1][1] = r3;
            }
#pragma unroll
            for (int mi = 0; mi < 4; mi++)
#pragma unroll
                for (int nf = 0; nf < 4; nf++)
                    mma16816(acc[mi][nf], af[mi], bf[nf]);
        }
        __syncthreads();
    }
}

// ---------------- GEMM kernels ------------------------------------------------
__global__ __launch_bounds__(256) void gemm1_mma_kernel() {
    float acc[4][4][4];
    const int m0 = blockIdx.y * 128, n0 = blockIdx.x * 128;
    mma_mainloop<KSPL>(g_A2, g_B1s, m0, n0, NC1, acc);
    const int lane = threadIdx.x & 31, w = threadIdx.x >> 5;
    const int wm = w & 1, wn = w >> 1;
#pragma unroll
    for (int mi = 0; mi < 4; mi++) {
        int row = m0 + wm * 64 + mi * 16 + (lane >> 2);
#pragma unroll
        for (int nf = 0; nf < 4; nf++) {
            int col = n0 + wn * 32 + nf * 8 + (lane & 3) * 2;
            *(float2*)(g_X + (size_t)row * LAT + col) =
                make_float2(acc[mi][nf][0], acc[mi][nf][1]);
            *(float2*)(g_X + (size_t)(row + 8) * LAT + col) =
                make_float2(acc[mi][nf][2], acc[mi][nf][3]);
        }
    }
}

__global__ __launch_bounds__(256) void gemm2_mma_kernel() {
    float acc[4][4][4];
    const int z  = blockIdx.z;                    // split-K half
    const int m0 = blockIdx.y * 128, n0 = blockIdx.x * 128;
    mma_mainloop<KSPL>(g_X2 + z * 48 * 64, g_W2s + z * 48 * 64, m0, n0, 48, acc);
    float* out = g_Zp + (size_t)z * NTOT * PROJ;
    const int lane = threadIdx.x & 31, w = threadIdx.x >> 5;
    const int wm = w & 1, wn = w >> 1;
#pragma unroll
    for (int mi = 0; mi < 4; mi++) {
        int row = m0 + wm * 64 + mi * 16 + (lane >> 2);
#pragma unroll
        for (int nf = 0; nf < 4; nf++) {
            int col = n0 + wn * 32 + nf * 8 + (lane & 3) * 2;
            *(float2*)(out + (size_t)row * PROJ + col) =
                make_float2(acc[mi][nf][0], acc[mi][nf][1]);
            *(float2*)(out + (size_t)(row + 8) * PROJ + col) =
                make_float2(acc[mi][nf][2], acc[mi][nf][3]);
        }
    }
}

// ---------------- BN stats ----------------------------------------------------
__global__ void bnstats_kernel() {
    int c  = blockIdx.x * 256 + threadIdx.x;
    int g  = blockIdx.y;
    int r0 = blockIdx.z * 256;
    const float* base = g_X + ((size_t)g * BATCH + r0) * LAT + c;
    float s = 0.f, sq = 0.f;
#pragma unroll 4
    for (int r = 0; r < 256; r++) {
        float x = base[(size_t)r * LAT];
        s += x; sq += x * x;
    }
    atomicAdd(&g_sum[g * LAT + c], s);
    atomicAdd(&g_sumsq[g * LAT + c], sq);
}

__global__ void bnfinal_kernel(const float* __restrict__ gamma,
                               const float* __restrict__ beta) {
    int idx = blockIdx.x * 256 + threadIdx.x;
    int c = idx & (LAT - 1);
    const float inv = 1.0f / (float)BATCH;
    float mu  = g_sum[idx] * inv;
    float var = g_sumsq[idx] * inv - mu * mu;
    float a = gamma[c] * rsqrtf(var + 1e-5f);
    g_bna[idx] = a;
    g_bnc[idx] = beta[c] - mu * a;
}

// ---------------- fused BN + ReLU + split-bf16 emit --------------------------
__global__ void bnrelu_split_kernel() {
    size_t i = (size_t)blockIdx.x * 256 + threadIdx.x;
    int row = (int)(i >> 10);
    int g   = row >> 11;
    int c2  = (int)i & 1023;
    const float* Ac = g_bna + g * LAT;
    const float* Cc = g_bnc + g * LAT;
    float2 x = ((const float2*)g_X)[i];
    float2 y;
    y.x = fmaxf(fmaf(x.x, Ac[2 * c2 + 0], Cc[2 * c2 + 0]), 0.f);
    y.y = fmaxf(fmaf(x.y, Ac[2 * c2 + 1], Cc[2 * c2 + 1]), 0.f);
    split_row_pair(y, (__nv_bfloat162*)(g_X2 + (size_t)row * KSPL), c2, 1);
}

// ---------------- rownorm: sum split-K parts + bias, normalize, emit splits --
__global__ void rownorm_kernel(const float* __restrict__ b2) {
    int row  = blockIdx.x * 8 + (threadIdx.x >> 5);
    int lane = threadIdx.x & 31;
    const float4* p0 = (const float4*)(g_Zp + (size_t)row * PROJ);
    const float4* p1 = (const float4*)(g_Zp + (size_t)(NTOT + row) * PROJ);
    const float4* bb = (const float4*)b2;
    float4 v0, v1;
    {
        float4 a = p0[lane], b = p1[lane], c = bb[lane];
        v0 = make_float4(a.x + b.x + c.x, a.y + b.y + c.y,
                         a.z + b.z + c.z, a.w + b.w + c.w);
        float4 d = p0[lane + 32], e = p1[lane + 32], f = bb[lane + 32];
        v1 = make_float4(d.x + e.x + f.x, d.y + e.y + f.y,
                         d.z + e.z + f.z, d.w + e.w + f.w);
    }
    float ss = v0.x * v0.x + v0.y * v0.y + v0.z * v0.z + v0.w * v0.w
             + v1.x * v1.x + v1.y * v1.y + v1.z * v1.z + v1.w * v1.w;
#pragma unroll
    for (int off = 16; off; off >>= 1) ss += __shfl_xor_sync(0xffffffffu, ss, off);
    float s = 1.41421356237f / fmaxf(sqrtf(ss), 1e-8f);   // sqrt(1/TEMP)/||z||
    v0.x *= s; v0.y *= s; v0.z *= s; v0.w *= s;
    v1.x *= s; v1.y *= s; v1.z *= s; v1.w *= s;

    __nv_bfloat162* ZA = (__nv_bfloat162*)(g_ZsA + (size_t)row * KZ);
    __nv_bfloat162* ZB = (__nv_bfloat162*)(g_ZsB + (size_t)row * KZ);
    float vv[8] = {v0.x, v0.y, v0.z, v0.w, v1.x, v1.y, v1.z, v1.w};
    int cbase[2] = {lane * 2, (lane + 32) * 2};   // bf162 pair index base (of 128)
#pragma unroll
    for (int h = 0; h < 2; h++) {
#pragma unroll
        for (int q = 0; q < 2; q++) {
            float x = vv[h * 4 + q * 2], y = vv[h * 4 + q * 2 + 1];
            __nv_bfloat16 hx = __float2bfloat16(x), hy = __float2bfloat16(y);
            __nv_bfloat16 lx = __float2bfloat16(x - __bfloat162float(hx));
            __nv_bfloat16 ly = __float2bfloat16(y - __bfloat162float(hy));
            __nv_bfloat162 hi2; hi2.x = hx; hi2.y = hy;
            __nv_bfloat162 lo2; lo2.x = lx; lo2.y = ly;
            int c2 = cbase[h] + q;                 // 0..127
            ZA[c2] = hi2; ZA[128 + c2] = lo2; ZA[256 + c2] = hi2;  // [h|l|h]
            ZB[c2] = hi2; ZB[128 + c2] = hi2; ZB[256 + c2] = lo2;  // [h|h|l]
        }
    }
}

// ---------------- tensorized sim + online exp-sum ----------------------------
__global__ __launch_bounds__(256) void sim_mma_kernel() {
    float acc[4][4][4];
    const int i0 = blockIdx.y * 128, j0 = blockIdx.x * 128;
    mma_mainloop<KZ>(g_ZsA, g_ZsB, i0, j0, NCZ, acc);

    const int lane = threadIdx.x & 31, w = threadIdx.x >> 5;
    const int wm = w & 1, wn = w >> 1;
    const int lr = lane >> 2;
    const int lc = (lane & 3) * 2;
#pragma unroll
    for (int mi = 0; mi < 4; mi++) {
        int row0 = i0 + wm * 64 + mi * 16 + lr;
        int row1 = row0 + 8;
        int p0 = (row0 < BATCH) ? row0 + BATCH : row0 - BATCH;
        int p1 = (row1 < BATCH) ? row1 + BATCH : row1 - BATCH;
        float rs0 = 0.f, rs1 = 0.f;
#pragma unroll
        for (int nf = 0; nf < 4; nf++) {
            int col = j0 + wn * 32 + nf * 8 + lc;
            float d00 = acc[mi][nf][0], d01 = acc[mi][nf][1];
            float d10 = acc[mi][nf][2], d11 = acc[mi][nf][3];
            if (col == p0)     g_pos[row0] = d00;
            if (col + 1 == p0) g_pos[row0] = d01;
            if (col == p1)     g_pos[row1] = d10;
            if (col + 1 == p1) g_pos[row1] = d11;
            rs0 += (col     != row0) ? fexp(d00 - 2.f) : 0.f;
            rs0 += (col + 1 != row0) ? fexp(d01 - 2.f) : 0.f;
            rs1 += (col     != row1) ? fexp(d10 - 2.f) : 0.f;
            rs1 += (col + 1 != row1) ? fexp(d11 - 2.f) : 0.f;
        }
        rs0 += __shfl_xor_sync(0xffffffffu, rs0, 1);
        rs0 += __shfl_xor_sync(0xffffffffu, rs0, 2);
        rs1 += __shfl_xor_sync(0xffffffffu, rs1, 1);
        rs1 += __shfl_xor_sync(0xffffffffu, rs1, 2);
        if ((lane & 3) == 0) {
            atomicAdd(&g_S[row0], rs0);
            atomicAdd(&g_S[row1], rs1);
        }
    }
}

// ---------------- final reduction --------------------------------------------
__global__ void loss_kernel(float* __restrict__ out) {
    __shared__ float red[256];
    int t = threadIdx.x;
    float s = 0.f;
    for (int i = t; i < NTOT; i += 256)
        s += 2.0f + logf(g_S[i]) - g_pos[i];
    red[t] = s;
    __syncthreads();
    for (int off = 128; off; off >>= 1) {
        if (t < off) red[t] += red[t + off];
        __syncthreads();
    }
    if (t == 0) out[0] = red[0] / (float)NTOT;
}

// ---------------- launch ------------------------------------------------------
extern "C" void kernel_launch(void* const* d_in, const int* in_sizes, int n_in,
                              void* d_out, int out_size) {
    const float* h_i   = (const float*)d_in[0];
    const float* h_j   = (const float*)d_in[1];
    const float* W1    = (const float*)d_in[2];
    const float* gamma = (const float*)d_in[3];
    const float* beta  = (const float*)d_in[4];
    const float* W2    = (const float*)d_in[5];
    const float* b2    = (const float*)d_in[6];
    float* out = (float*)d_out;

    const int GEMM_SMEM = 3 * 32768;   // 98304
    cudaFuncSetAttribute(gemm1_mma_kernel, cudaFuncAttributeMaxDynamicSharedMemorySize, GEMM_SMEM);
    cudaFuncSetAttribute(gemm2_mma_kernel, cudaFuncAttributeMaxDynamicSharedMemorySize, GEMM_SMEM);
    cudaFuncSetAttribute(sim_mma_kernel,   cudaFuncAttributeMaxDynamicSharedMemorySize, GEMM_SMEM);

    init_kernel<<<16, 256>>>();
    splitA_kernel<<<NTOT * 1024 / 256, 256>>>(h_i, h_j);
    splitW_kernel<<<(LAT + PROJ) * 1024 / 256, 256>>>(W1, W2);
    gemm1_mma_kernel<<<dim3(16, 32), 256, GEMM_SMEM>>>();
    bnstats_kernel<<<dim3(8, 2, 8), 256>>>();
    bnfinal_kernel<<<16, 256>>>(gamma, beta);
    bnrelu_split_kernel<<<NTOT * 1024 / 256, 256>>>();
    gemm2_mma_kernel<<<dim3(2, 32, 2), 256, GEMM_SMEM>>>();
    rownorm_kernel<<<512, 256>>>(b2);
    sim_mma_kernel<<<dim3(32, 32), 256, GEMM_SMEM>>>();
    loss_kernel<<<1, 256>>>(out);
}

// round 5
// speedup vs baseline: 4.0786x; 1.0955x over previous
#include <cuda_runtime.h>
#include <cuda_bf16.h>
#include <math.h>
#include <stdint.h>

#define BATCH 2048
#define NTOT  4096
#define LAT   2048
#define PROJ  256
#define KPG   4096          // physical K for gemm operands: [hi | lo]
#define KPZ   512           // physical K for sim operand:   [hi | lo]
#define NCK1  96            // logical chunks gemm1/2 (3 * 2048 / 64)
#define NCKZ  12            // logical chunks sim     (3 * 256 / 64)

// ---------------- device scratch (no runtime allocation allowed) -------------
__device__ __nv_bfloat16 g_A2[(size_t)NTOT * KPG];    // [Hh | Hl]
__device__ __nv_bfloat16 g_B1s[(size_t)LAT * KPG];    // [W1h | W1l]
__device__ __nv_bfloat16 g_W2s[(size_t)PROJ * KPG];   // [W2h | W2l]
__device__ __nv_bfloat16 g_X2[(size_t)NTOT * KPG];    // [Xh | Xl]
__device__ __nv_bfloat16 g_Zs[(size_t)NTOT * KPZ];    // normalized Z [h | l]
__device__ float g_X[(size_t)NTOT * LAT];
__device__ float g_Zp[(size_t)2 * NTOT * PROJ];       // split-K partials
__device__ float g_sum[2 * LAT];
__device__ float g_sumsq[2 * LAT];
__device__ float g_bna[2 * LAT];
__device__ float g_bnc[2 * LAT];
__device__ float g_S[NTOT];
__device__ float g_pos[NTOT];

// ---------------- PTX helpers (baseline ISA only) ----------------------------
__device__ __forceinline__ uint32_t smem_u32(const void* p) {
    return (uint32_t)__cvta_generic_to_shared(p);
}
__device__ __forceinline__ void cp16(uint32_t dst, const void* src) {
    asm volatile("cp.async.cg.shared.global [%0], [%1], 16;" :: "r"(dst), "l"(src));
}
__device__ __forceinline__ void cp_commit() { asm volatile("cp.async.commit_group;"); }
__device__ __forceinline__ void cp_wait1()  { asm volatile("cp.async.wait_group 1;"); }
__device__ __forceinline__ void cp_wait0()  { asm volatile("cp.async.wait_group 0;"); }
__device__ __forceinline__ void ldsm_x4(uint32_t a, uint32_t& r0, uint32_t& r1,
                                        uint32_t& r2, uint32_t& r3) {
    asm volatile("ldmatrix.sync.aligned.m8n8.x4.shared.b16 {%0,%1,%2,%3}, [%4];"
                 : "=r"(r0), "=r"(r1), "=r"(r2), "=r"(r3) : "r"(a));
}
__device__ __forceinline__ void mma16816(float* c, const uint32_t* a, const uint32_t* b) {
    asm volatile("mma.sync.aligned.m16n8k16.row.col.f32.bf16.bf16.f32 "
                 "{%0,%1,%2,%3}, {%4,%5,%6,%7}, {%8,%9}, {%0,%1,%2,%3};"
                 : "+f"(c[0]), "+f"(c[1]), "+f"(c[2]), "+f"(c[3])
                 : "r"(a[0]), "r"(a[1]), "r"(a[2]), "r"(a[3]), "r"(b[0]), "r"(b[1]));
}

// FMA-only exp for y in ~[-4.1, 0.1]
__device__ __forceinline__ float fexp(float y) {
    float t = y * 1.4426950408889634f;
    float n = rintf(t);
    float f = t - n;
    float p =              1.5403530e-4f;
    p = fmaf(p, f, 1.3333558e-3f);
    p = fmaf(p, f, 9.6181291e-3f);
    p = fmaf(p, f, 5.5504109e-2f);
    p = fmaf(p, f, 2.4022651e-1f);
    p = fmaf(p, f, 6.9314718e-1f);
    p = fmaf(p, f, 1.0f);
    int e = ((int)n + 127) << 23;
    return p * __int_as_float(e);
}

// ---------------- init --------------------------------------------------------
__global__ void init_kernel() {
    int i = blockIdx.x * 256 + threadIdx.x;
    if (i < NTOT) g_S[i] = 0.f;
    if (i < 2 * LAT) { g_sum[i] = 0.f; g_sumsq[i] = 0.f; }
}

// ---------------- split fp32 -> [hi | lo] bf16 --------------------------------
__device__ __forceinline__ void split_pair(const float2 v, __nv_bfloat162* drow,
                                           int c2, int half_pairs) {
    __nv_bfloat16 hx = __float2bfloat16(v.x), hy = __float2bfloat16(v.y);
    __nv_bfloat16 lx = __float2bfloat16(v.x - __bfloat162float(hx));
    __nv_bfloat16 ly = __float2bfloat16(v.y - __bfloat162float(hy));
    __nv_bfloat162 hi2; hi2.x = hx; hi2.y = hy;
    __nv_bfloat162 lo2; lo2.x = lx; lo2.y = ly;
    drow[c2] = hi2;
    drow[half_pairs + c2] = lo2;
}

__global__ void splitA_kernel(const float* __restrict__ hi_,
                              const float* __restrict__ hj_) {
    size_t i = (size_t)blockIdx.x * 256 + threadIdx.x;   // NTOT*1024 pairs
    int row = (int)(i >> 10);
    int c2  = (int)i & 1023;
    float2 v = (row < BATCH) ? ((const float2*)hi_)[i]
                             : ((const float2*)hj_)[i - (size_t)BATCH * 1024];
    split_pair(v, (__nv_bfloat162*)(g_A2 + (size_t)row * KPG), c2, 1024);
}

__global__ void splitW_kernel(const float* __restrict__ W1,
                              const float* __restrict__ W2) {
    size_t i = (size_t)blockIdx.x * 256 + threadIdx.x;   // (LAT+PROJ)*1024 pairs
    int row = (int)(i >> 10);
    int c2  = (int)i & 1023;
    if (row < LAT) {
        float2 v = ((const float2*)W1)[i];
        split_pair(v, (__nv_bfloat162*)(g_B1s + (size_t)row * KPG), c2, 1024);
    } else {
        float2 v = ((const float2*)W2)[i - (size_t)LAT * 1024];
        split_pair(v, (__nv_bfloat162*)(g_W2s + (size_t)(row - LAT) * KPG), c2, 1024);
    }
}

// ---------------- shared MMA mainloop (3-stage, single sync/iter) ------------
// CTA tile 128x128, BK=64 bf16 (128B rows, xor swizzle), 256 threads,
// 8 warps (2m x 4n), warp tile 64x32. Logical K-chunks map to [hi|lo] physical:
//   A: [Ah | Al | Ah]  -> mapA(c) = c < 2*KH ? c : c - 2*KH
//   B: [Bh | Bh | Bl]  -> mapB(c) = c < KH   ? c : c - KH
template <int KPHYS, int KH>
__device__ __forceinline__ void mma_mainloop(const __nv_bfloat16* __restrict__ A,
                                             const __nv_bfloat16* __restrict__ B,
                                             int m0, int n0, int c0, int nck,
                                             float acc[4][4][4]) {
    extern __shared__ char smem[];
    const uint32_t sb = smem_u32(smem);
    const int tid  = threadIdx.x;
    const int lane = tid & 31;
    const int w    = tid >> 5;
    const int wm   = w & 1;
    const int wn   = w >> 1;

    auto load_tile = [&](int c) {                 // c relative to c0
        const int cl = c0 + c;                    // logical chunk
        const int kA = ((cl < 2 * KH) ? cl : cl - 2 * KH) * 64;
        const int kB = ((cl < KH) ? cl : cl - KH) * 64;
        const uint32_t sA = sb + (uint32_t)(c % 3) * 32768u;
        const uint32_t sB = sA + 16384u;
#pragma unroll
        for (int i = 0; i < 4; i++) {
            int idx = i * 256 + tid;
            int row = idx >> 3, ch = idx & 7;
            uint32_t dst = (uint32_t)row * 128 + (uint32_t)((ch ^ (row & 7)) * 16);
            cp16(sA + dst, A + (size_t)(m0 + row) * KPHYS + kA + ch * 8);
            cp16(sB + dst, B + (size_t)(n0 + row) * KPHYS + kB + ch * 8);
        }
        cp_commit();
    };

#pragma unroll
    for (int i = 0; i < 4; i++)
#pragma unroll
        for (int j = 0; j < 4; j++)
#pragma unroll
            for (int q = 0; q < 4; q++) acc[i][j][q] = 0.f;

    const int rA   = wm * 64 + (lane & 15);
    const int khA  = lane >> 4;
    const int rB   = wn * 32 + ((lane >> 4) << 3) + (lane & 7);
    const int khB  = (lane >> 3) & 1;
    const int rlow = lane & 7;

    load_tile(0);
    load_tile(1);

    for (int c = 0; c < nck; c++) {
        if (c < nck - 1) cp_wait1(); else cp_wait0();
        __syncthreads();                     // single barrier per iteration
        if (c + 2 < nck) load_tile(c + 2);   // distinct buffer; overlaps compute
        const uint32_t sA = sb + (uint32_t)(c % 3) * 32768u;
        const uint32_t sB = sA + 16384u;
#pragma unroll
        for (int ks = 0; ks < 4; ks++) {
            uint32_t af[4][4], bf[4][2];
#pragma unroll
            for (int mi = 0; mi < 4; mi++) {
                uint32_t a = sA + (uint32_t)(rA + mi * 16) * 128
                           + (uint32_t)((((ks * 2) + khA) ^ rlow) * 16);
                ldsm_x4(a, af[mi][0], af[mi][1], af[mi][2], af[mi][3]);
            }
#pragma unroll
            for (int np = 0; np < 2; np++) {
                uint32_t r0, r1, r2, r3;
                uint32_t a = sB + (uint32_t)(rB + np * 16) * 128
                           + (uint32_t)((((ks * 2) + khB) ^ rlow) * 16);
                ldsm_x4(a, r0, r1, r2, r3);
                bf[np * 2 + 0][0] = r0; bf[np * 2 + 0][1] = r1;
                bf[np * 2 + 1][0] = r2; bf[np * 2 + 1][1] = r3;
            }
#pragma unroll
            for (int mi = 0; mi < 4; mi++)
#pragma unroll
                for (int nf = 0; nf < 4; nf++)
                    mma16816(acc[mi][nf], af[mi], bf[nf]);
        }
    }
}

// ---------------- GEMM kernels ------------------------------------------------
__global__ __launch_bounds__(256, 2) void gemm1_mma_kernel() {
    float acc[4][4][4];
    const int m0 = blockIdx.y * 128, n0 = blockIdx.x * 128;
    mma_mainloop<KPG, 32>(g_A2, g_B1s, m0, n0, 0, NCK1, acc);
    const int lane = threadIdx.x & 31, w = threadIdx.x >> 5;
    const int wm = w & 1, wn = w >> 1;
#pragma unroll
    for (int mi = 0; mi < 4; mi++) {
        int row = m0 + wm * 64 + mi * 16 + (lane >> 2);
#pragma unroll
        for (int nf = 0; nf < 4; nf++) {
            int col = n0 + wn * 32 + nf * 8 + (lane & 3) * 2;
            *(float2*)(g_X + (size_t)row * LAT + col) =
                make_float2(acc[mi][nf][0], acc[mi][nf][1]);
            *(float2*)(g_X + (size_t)(row + 8) * LAT + col) =
                make_float2(acc[mi][nf][2], acc[mi][nf][3]);
        }
    }
}

__global__ __launch_bounds__(256, 2) void gemm2_mma_kernel() {
    float acc[4][4][4];
    const int z  = blockIdx.z;
    const int m0 = blockIdx.y * 128, n0 = blockIdx.x * 128;
    mma_mainloop<KPG, 32>(g_X2, g_W2s, m0, n0, z * 48, 48, acc);
    float* out = g_Zp + (size_t)z * NTOT * PROJ;
    const int lane = threadIdx.x & 31, w = threadIdx.x >> 5;
    const int wm = w & 1, wn = w >> 1;
#pragma unroll
    for (int mi = 0; mi < 4; mi++) {
        int row = m0 + wm * 64 + mi * 16 + (lane >> 2);
#pragma unroll
        for (int nf = 0; nf < 4; nf++) {
            int col = n0 + wn * 32 + nf * 8 + (lane & 3) * 2;
            *(float2*)(out + (size_t)row * PROJ + col) =
                make_float2(acc[mi][nf][0], acc[mi][nf][1]);
            *(float2*)(out + (size_t)(row + 8) * PROJ + col) =
                make_float2(acc[mi][nf][2], acc[mi][nf][3]);
        }
    }
}

// ---------------- BN stats ----------------------------------------------------
__global__ void bnstats_kernel() {
    int c  = blockIdx.x * 256 + threadIdx.x;
    int g  = blockIdx.y;
    int r0 = blockIdx.z * 256;
    const float* base = g_X + ((size_t)g * BATCH + r0) * LAT + c;
    float s = 0.f, sq = 0.f;
#pragma unroll 4
    for (int r = 0; r < 256; r++) {
        float x = base[(size_t)r * LAT];
        s += x; sq += x * x;
    }
    atomicAdd(&g_sum[g * LAT + c], s);
    atomicAdd(&g_sumsq[g * LAT + c], sq);
}

__global__ void bnfinal_kernel(const float* __restrict__ gamma,
                               const float* __restrict__ beta) {
    int idx = blockIdx.x * 256 + threadIdx.x;
    int c = idx & (LAT - 1);
    const float inv = 1.0f / (float)BATCH;
    float mu  = g_sum[idx] * inv;
    float var = g_sumsq[idx] * inv - mu * mu;
    float a = gamma[c] * rsqrtf(var + 1e-5f);
    g_bna[idx] = a;
    g_bnc[idx] = beta[c] - mu * a;
}

// ---------------- fused BN + ReLU + [hi|lo] emit ------------------------------
__global__ void bnrelu_split_kernel() {
    size_t i = (size_t)blockIdx.x * 256 + threadIdx.x;
    int row = (int)(i >> 10);
    int g   = row >> 11;
    int c2  = (int)i & 1023;
    const float* Ac = g_bna + g * LAT;
    const float* Cc = g_bnc + g * LAT;
    float2 x = ((const float2*)g_X)[i];
    float2 y;
    y.x = fmaxf(fmaf(x.x, Ac[2 * c2 + 0], Cc[2 * c2 + 0]), 0.f);
    y.y = fmaxf(fmaf(x.y, Ac[2 * c2 + 1], Cc[2 * c2 + 1]), 0.f);
    split_pair(y, (__nv_bfloat162*)(g_X2 + (size_t)row * KPG), c2, 1024);
}

// ---------------- rownorm: sum split-K parts + bias, normalize, emit ----------
__global__ void rownorm_kernel(const float* __restrict__ b2) {
    int row  = blockIdx.x * 8 + (threadIdx.x >> 5);
    int lane = threadIdx.x & 31;
    const float4* p0 = (const float4*)(g_Zp + (size_t)row * PROJ);
    const float4* p1 = (const float4*)(g_Zp + (size_t)(NTOT + row) * PROJ);
    const float4* bb = (const float4*)b2;
    float4 v0, v1;
    {
        float4 a = p0[lane], b = p1[lane], c = bb[lane];
        v0 = make_float4(a.x + b.x + c.x, a.y + b.y + c.y,
                         a.z + b.z + c.z, a.w + b.w + c.w);
        float4 d = p0[lane + 32], e = p1[lane + 32], f = bb[lane + 32];
        v1 = make_float4(d.x + e.x + f.x, d.y + e.y + f.y,
                         d.z + e.z + f.z, d.w + e.w + f.w);
    }
    float ss = v0.x * v0.x + v0.y * v0.y + v0.z * v0.z + v0.w * v0.w
             + v1.x * v1.x + v1.y * v1.y + v1.z * v1.z + v1.w * v1.w;
#pragma unroll
    for (int off = 16; off; off >>= 1) ss += __shfl_xor_sync(0xffffffffu, ss, off);
    float s = 1.41421356237f / fmaxf(sqrtf(ss), 1e-8f);   // sqrt(1/TEMP)/||z||
    v0.x *= s; v0.y *= s; v0.z *= s; v0.w *= s;
    v1.x *= s; v1.y *= s; v1.z *= s; v1.w *= s;

    __nv_bfloat162* Z = (__nv_bfloat162*)(g_Zs + (size_t)row * KPZ);
    float vv[8] = {v0.x, v0.y, v0.z, v0.w, v1.x, v1.y, v1.z, v1.w};
    int cbase[2] = {lane * 2, (lane + 32) * 2};
#pragma unroll
    for (int h = 0; h < 2; h++) {
#pragma unroll
        for (int q = 0; q < 2; q++) {
            float2 xy = make_float2(vv[h * 4 + q * 2], vv[h * 4 + q * 2 + 1]);
            split_pair(xy, Z, cbase[h] + q, 128);
        }
    }
}

// ---------------- symmetric tensorized sim + online exp-sum ------------------
// Upper-triangle blocks only (b >= a). Off-diagonal blocks feed row sums AND
// column sums (sim is exactly symmetric under the split: Zh.Zh+Zl.Zh+Zh.Zl).
__global__ __launch_bounds__(256, 2) void sim_mma_kernel() {
    const int a = blockIdx.y, b = blockIdx.x;
    if (b < a) return;
    float acc[4][4][4];
    const int i0 = a * 128, j0 = b * 128;
    mma_mainloop<KPZ, 4>(g_Zs, g_Zs, i0, j0, 0, NCKZ, acc);

    const int lane = threadIdx.x & 31, w = threadIdx.x >> 5;
    const int wm = w & 1, wn = w >> 1;
    const int lr = lane >> 2;
    const int lc = (lane & 3) * 2;
    const bool offd = (a != b);

    float cs[4][2];
#pragma unroll
    for (int nf = 0; nf < 4; nf++) { cs[nf][0] = 0.f; cs[nf][1] = 0.f; }

#pragma unroll
    for (int mi = 0; mi < 4; mi++) {
        int row0 = i0 + wm * 64 + mi * 16 + lr;
        int row1 = row0 + 8;
        int p0 = (row0 < BATCH) ? row0 + BATCH : row0 - BATCH;
        int p1 = (row1 < BATCH) ? row1 + BATCH : row1 - BATCH;
        float rs0 = 0.f, rs1 = 0.f;
#pragma unroll
        for (int nf = 0; nf < 4; nf++) {
            int col = j0 + wn * 32 + nf * 8 + lc;
            float d00 = acc[mi][nf][0], d01 = acc[mi][nf][1];
            float d10 = acc[mi][nf][2], d11 = acc[mi][nf][3];
            if (col == p0)     { g_pos[row0] = d00; g_pos[col]     = d00; }
            if (col + 1 == p0) { g_pos[row0] = d01; g_pos[col + 1] = d01; }
            if (col == p1)     { g_pos[row1] = d10; g_pos[col]     = d10; }
            if (col + 1 == p1) { g_pos[row1] = d11; g_pos[col + 1] = d11; }
            float e00 = (col     != row0) ? fexp(d00 - 2.f) : 0.f;
            float e01 = (col + 1 != row0) ? fexp(d01 - 2.f) : 0.f;
            float e10 = (col     != row1) ? fexp(d10 - 2.f) : 0.f;
            float e11 = (col + 1 != row1) ? fexp(d11 - 2.f) : 0.f;
            rs0 += e00 + e01;
            rs1 += e10 + e11;
            if (offd) { cs[nf][0] += e00 + e10; cs[nf][1] += e01 + e11; }
        }
        rs0 += __shfl_xor_sync(0xffffffffu, rs0, 1);
        rs0 += __shfl_xor_sync(0xffffffffu, rs0, 2);
        rs1 += __shfl_xor_sync(0xffffffffu, rs1, 1);
        rs1 += __shfl_xor_sync(0xffffffffu, rs1, 2);
        if ((lane & 3) == 0) {
            atomicAdd(&g_S[row0], rs0);
            atomicAdd(&g_S[row1], rs1);
        }
    }
    if (offd) {
#pragma unroll
        for (int nf = 0; nf < 4; nf++) {
#pragma unroll
            for (int q = 0; q < 2; q++) {
                float v = cs[nf][q];
                v += __shfl_xor_sync(0xffffffffu, v, 4);
                v += __shfl_xor_sync(0xffffffffu, v, 8);
                v += __shfl_xor_sync(0xffffffffu, v, 16);
                if (lr == 0)
                    atomicAdd(&g_S[j0 + wn * 32 + nf * 8 + lc + q], v);
            }
        }
    }
}

// ---------------- final reduction --------------------------------------------
__global__ void loss_kernel(float* __restrict__ out) {
    __shared__ float red[256];
    int t = threadIdx.x;
    float s = 0.f;
    for (int i = t; i < NTOT; i += 256)
        s += 2.0f + logf(g_S[i]) - g_pos[i];
    red[t] = s;
    __syncthreads();
    for (int off = 128; off; off >>= 1) {
        if (t < off) red[t] += red[t + off];
        __syncthreads();
    }
    if (t == 0) out[0] = red[0] / (float)NTOT;
}

// ---------------- launch ------------------------------------------------------
extern "C" void kernel_launch(void* const* d_in, const int* in_sizes, int n_in,
                              void* d_out, int out_size) {
    const float* h_i   = (const float*)d_in[0];
    const float* h_j   = (const float*)d_in[1];
    const float* W1    = (const float*)d_in[2];
    const float* gamma = (const float*)d_in[3];
    const float* beta  = (const float*)d_in[4];
    const float* W2    = (const float*)d_in[5];
    const float* b2    = (const float*)d_in[6];
    float* out = (float*)d_out;

    const int GEMM_SMEM = 3 * 32768;   // 98304
    cudaFuncSetAttribute(gemm1_mma_kernel, cudaFuncAttributeMaxDynamicSharedMemorySize, GEMM_SMEM);
    cudaFuncSetAttribute(gemm2_mma_kernel, cudaFuncAttributeMaxDynamicSharedMemorySize, GEMM_SMEM);
    cudaFuncSetAttribute(sim_mma_kernel,   cudaFuncAttributeMaxDynamicSharedMemorySize, GEMM_SMEM);

    init_kernel<<<16, 256>>>();
    splitA_kernel<<<NTOT * 1024 / 256, 256>>>(h_i, h_j);
    splitW_kernel<<<(LAT + PROJ) * 1024 / 256, 256>>>(W1, W2);
    gemm1_mma_kernel<<<dim3(16, 32), 256, GEMM_SMEM>>>();
    bnstats_kernel<<<dim3(8, 2, 8), 256>>>();
    bnfinal_kernel<<<16, 256>>>(gamma, beta);
    bnrelu_split_kernel<<<NTOT * 1024 / 256, 256>>>();
    gemm2_mma_kernel<<<dim3(2, 32, 2), 256, GEMM_SMEM>>>();
    rownorm_kernel<<<512, 256>>>(b2);
    sim_mma_kernel<<<dim3(32, 32), 256, GEMM_SMEM>>>();
    loss_kernel<<<1, 256>>>(out);
}

// round 6
// speedup vs baseline: 5.8430x; 1.4326x over previous
#include <cuda_runtime.h>
#include <cuda_bf16.h>
#include <math.h>
#include <stdint.h>

#define BATCH 2048
#define NTOT  4096
#define LAT   2048
#define PROJ  256
#define KPG   4096          // physical K for gemm operands: [hi | lo]
#define KPZ   512           // physical K for sim operand:   [hi | lo]
#define NCK1  64            // logical chunks gemm1/2: 2-term (Ah+Al)*Bh
#define NCKZ  12            // logical chunks sim: 3-term

// ---------------- device scratch (no runtime allocation allowed) -------------
__device__ __nv_bfloat16 g_A2[(size_t)NTOT * KPG];    // [Hh | Hl]
__device__ __nv_bfloat16 g_B1s[(size_t)LAT * KPG];    // [W1h | W1l]
__device__ __nv_bfloat16 g_W2s[(size_t)PROJ * KPG];   // [W2h | W2l]
__device__ __nv_bfloat16 g_X2[(size_t)NTOT * KPG];    // [Xh | Xl]
__device__ __nv_bfloat16 g_Zs[(size_t)NTOT * KPZ];    // normalized Z [h | l]
__device__ float g_X[(size_t)NTOT * LAT];
__device__ float g_Zp[(size_t)2 * NTOT * PROJ];       // split-K partials
__device__ float g_sum[2 * LAT];
__device__ float g_sumsq[2 * LAT];
__device__ float g_bna[2 * LAT];
__device__ float g_bnc[2 * LAT];
__device__ float g_S[NTOT];
__device__ float g_pos[NTOT];

// ---------------- PTX helpers (baseline ISA only) ----------------------------
__device__ __forceinline__ uint32_t smem_u32(const void* p) {
    return (uint32_t)__cvta_generic_to_shared(p);
}
__device__ __forceinline__ void cp16(uint32_t dst, const void* src) {
    asm volatile("cp.async.cg.shared.global [%0], [%1], 16;" :: "r"(dst), "l"(src));
}
__device__ __forceinline__ void cp_commit() { asm volatile("cp.async.commit_group;"); }
__device__ __forceinline__ void cp_wait1()  { asm volatile("cp.async.wait_group 1;"); }
__device__ __forceinline__ void cp_wait0()  { asm volatile("cp.async.wait_group 0;"); }
__device__ __forceinline__ void ldsm_x4(uint32_t a, uint32_t& r0, uint32_t& r1,
                                        uint32_t& r2, uint32_t& r3) {
    asm volatile("ldmatrix.sync.aligned.m8n8.x4.shared.b16 {%0,%1,%2,%3}, [%4];"
                 : "=r"(r0), "=r"(r1), "=r"(r2), "=r"(r3) : "r"(a));
}
__device__ __forceinline__ void mma16816(float* c, const uint32_t* a, const uint32_t* b) {
    asm volatile("mma.sync.aligned.m16n8k16.row.col.f32.bf16.bf16.f32 "
                 "{%0,%1,%2,%3}, {%4,%5,%6,%7}, {%8,%9}, {%0,%1,%2,%3};"
                 : "+f"(c[0]), "+f"(c[1]), "+f"(c[2]), "+f"(c[3])
                 : "r"(a[0]), "r"(a[1]), "r"(a[2]), "r"(a[3]), "r"(b[0]), "r"(b[1]));
}

// FMA-only exp for y in ~[-4.1, 0.1]
__device__ __forceinline__ float fexp(float y) {
    float t = y * 1.4426950408889634f;
    float n = rintf(t);
    float f = t - n;
    float p =              1.5403530e-4f;
    p = fmaf(p, f, 1.3333558e-3f);
    p = fmaf(p, f, 9.6181291e-3f);
    p = fmaf(p, f, 5.5504109e-2f);
    p = fmaf(p, f, 2.4022651e-1f);
    p = fmaf(p, f, 6.9314718e-1f);
    p = fmaf(p, f, 1.0f);
    int e = ((int)n + 127) << 23;
    return p * __int_as_float(e);
}

// ---------------- init --------------------------------------------------------
__global__ void init_kernel() {
    int i = blockIdx.x * 256 + threadIdx.x;
    if (i < NTOT) g_S[i] = 0.f;
    if (i < 2 * LAT) { g_sum[i] = 0.f; g_sumsq[i] = 0.f; }
}

// ---------------- split fp32 -> [hi | lo] bf16 --------------------------------
__device__ __forceinline__ void split_pair(const float2 v, __nv_bfloat162* drow,
                                           int c2, int half_pairs) {
    __nv_bfloat16 hx = __float2bfloat16(v.x), hy = __float2bfloat16(v.y);
    __nv_bfloat16 lx = __float2bfloat16(v.x - __bfloat162float(hx));
    __nv_bfloat16 ly = __float2bfloat16(v.y - __bfloat162float(hy));
    __nv_bfloat162 hi2; hi2.x = hx; hi2.y = hy;
    __nv_bfloat162 lo2; lo2.x = lx; lo2.y = ly;
    drow[c2] = hi2;
    drow[half_pairs + c2] = lo2;
}

__global__ void splitA_kernel(const float* __restrict__ hi_,
                              const float* __restrict__ hj_) {
    size_t i = (size_t)blockIdx.x * 256 + threadIdx.x;   // NTOT*1024 pairs
    int row = (int)(i >> 10);
    int c2  = (int)i & 1023;
    float2 v = (row < BATCH) ? ((const float2*)hi_)[i]
                             : ((const float2*)hj_)[i - (size_t)BATCH * 1024];
    split_pair(v, (__nv_bfloat162*)(g_A2 + (size_t)row * KPG), c2, 1024);
}

__global__ void splitW_kernel(const float* __restrict__ W1,
                              const float* __restrict__ W2) {
    size_t i = (size_t)blockIdx.x * 256 + threadIdx.x;   // (LAT+PROJ)*1024 pairs
    int row = (int)(i >> 10);
    int c2  = (int)i & 1023;
    if (row < LAT) {
        float2 v = ((const float2*)W1)[i];
        split_pair(v, (__nv_bfloat162*)(g_B1s + (size_t)row * KPG), c2, 1024);
    } else {
        float2 v = ((const float2*)W2)[i - (size_t)LAT * 1024];
        split_pair(v, (__nv_bfloat162*)(g_W2s + (size_t)(row - LAT) * KPG), c2, 1024);
    }
}

// ---------------- shared MMA mainloop (3-stage, single sync/iter) ------------
// CTA tile 128x128, BK=64 bf16 (128B rows, xor swizzle), 256 threads,
// 8 warps (2m x 4n), warp tile 64x32. Logical K-chunks map to [hi|lo] physical:
//   A: mapA(c) = c < 2*KH ? c : c - 2*KH      (covers [Ah|Al] then wraps)
//   B: mapB(c) = c < KH   ? c : c - KH        (hi reused, then lo)
// 2-term (gemm1/2): nck = 2*KH -> A=[Ah|Al], B=[Bh|Bh]
// 3-term (sim):     nck = 3*KH -> A=[Ah|Al|Ah], B=[Bh|Bh|Bl]
template <int KPHYS, int KH>
__device__ __forceinline__ void mma_mainloop(const __nv_bfloat16* __restrict__ A,
                                             const __nv_bfloat16* __restrict__ B,
                                             int m0, int n0, int c0, int nck,
                                             float acc[4][4][4]) {
    extern __shared__ char smem[];
    const uint32_t sb = smem_u32(smem);
    const int tid  = threadIdx.x;
    const int lane = tid & 31;
    const int w    = tid >> 5;
    const int wm   = w & 1;
    const int wn   = w >> 1;

    auto load_tile = [&](int c) {
        const int cl = c0 + c;
        const int kA = ((cl < 2 * KH) ? cl : cl - 2 * KH) * 64;
        const int kB = ((cl < KH) ? cl : cl - KH) * 64;
        const uint32_t sA = sb + (uint32_t)(c % 3) * 32768u;
        const uint32_t sB = sA + 16384u;
#pragma unroll
        for (int i = 0; i < 4; i++) {
            int idx = i * 256 + tid;
            int row = idx >> 3, ch = idx & 7;
            uint32_t dst = (uint32_t)row * 128 + (uint32_t)((ch ^ (row & 7)) * 16);
            cp16(sA + dst, A + (size_t)(m0 + row) * KPHYS + kA + ch * 8);
            cp16(sB + dst, B + (size_t)(n0 + row) * KPHYS + kB + ch * 8);
        }
        cp_commit();
    };

#pragma unroll
    for (int i = 0; i < 4; i++)
#pragma unroll
        for (int j = 0; j < 4; j++)
#pragma unroll
            for (int q = 0; q < 4; q++) acc[i][j][q] = 0.f;

    const int rA   = wm * 64 + (lane & 15);
    const int khA  = lane >> 4;
    const int rB   = wn * 32 + ((lane >> 4) << 3) + (lane & 7);
    const int khB  = (lane >> 3) & 1;
    const int rlow = lane & 7;

    load_tile(0);
    load_tile(1);

    for (int c = 0; c < nck; c++) {
        if (c < nck - 1) cp_wait1(); else cp_wait0();
        __syncthreads();
        if (c + 2 < nck) load_tile(c + 2);
        const uint32_t sA = sb + (uint32_t)(c % 3) * 32768u;
        const uint32_t sB = sA + 16384u;
#pragma unroll
        for (int ks = 0; ks < 4; ks++) {
            uint32_t af[4][4], bf[4][2];
#pragma unroll
            for (int mi = 0; mi < 4; mi++) {
                uint32_t a = sA + (uint32_t)(rA + mi * 16) * 128
                           + (uint32_t)((((ks * 2) + khA) ^ rlow) * 16);
                ldsm_x4(a, af[mi][0], af[mi][1], af[mi][2], af[mi][3]);
            }
#pragma unroll
            for (int np = 0; np < 2; np++) {
                uint32_t r0, r1, r2, r3;
                uint32_t a = sB + (uint32_t)(rB + np * 16) * 128
                           + (uint32_t)((((ks * 2) + khB) ^ rlow) * 16);
                ldsm_x4(a, r0, r1, r2, r3);
                bf[np * 2 + 0][0] = r0; bf[np * 2 + 0][1] = r1;
                bf[np * 2 + 1][0] = r2; bf[np * 2 + 1][1] = r3;
            }
#pragma unroll
            for (int mi = 0; mi < 4; mi++)
#pragma unroll
                for (int nf = 0; nf < 4; nf++)
                    mma16816(acc[mi][nf], af[mi], bf[nf]);
        }
    }
}

// ---------------- GEMM1 (+fused BN column stats) ------------------------------
__global__ __launch_bounds__(256, 2) void gemm1_mma_kernel() {
    float acc[4][4][4];
    const int m0 = blockIdx.y * 128, n0 = blockIdx.x * 128;
    mma_mainloop<KPG, 32>(g_A2, g_B1s, m0, n0, 0, NCK1, acc);
    const int lane = threadIdx.x & 31, w = threadIdx.x >> 5;
    const int wm = w & 1, wn = w >> 1;
#pragma unroll
    for (int mi = 0; mi < 4; mi++) {
        int row = m0 + wm * 64 + mi * 16 + (lane >> 2);
#pragma unroll
        for (int nf = 0; nf < 4; nf++) {
            int col = n0 + wn * 32 + nf * 8 + (lane & 3) * 2;
            *(float2*)(g_X + (size_t)row * LAT + col) =
                make_float2(acc[mi][nf][0], acc[mi][nf][1]);
            *(float2*)(g_X + (size_t)(row + 8) * LAT + col) =
                make_float2(acc[mi][nf][2], acc[mi][nf][3]);
        }
    }
    // fused BN stats: per-column sum/sumsq over this tile's 128 rows
    const int g = m0 >> 11;
#pragma unroll
    for (int nf = 0; nf < 4; nf++) {
#pragma unroll
        for (int q = 0; q < 2; q++) {
            float s = 0.f, sq = 0.f;
#pragma unroll
            for (int mi = 0; mi < 4; mi++) {
                float v0 = acc[mi][nf][q];
                float v1 = acc[mi][nf][q + 2];
                s += v0 + v1;
                sq = fmaf(v0, v0, sq);
                sq = fmaf(v1, v1, sq);
            }
#pragma unroll
            for (int off = 4; off <= 16; off <<= 1) {
                s  += __shfl_xor_sync(0xffffffffu, s, off);
                sq += __shfl_xor_sync(0xffffffffu, sq, off);
            }
            if ((lane >> 2) == 0) {
                int col = n0 + wn * 32 + nf * 8 + (lane & 3) * 2 + q;
                atomicAdd(&g_sum[g * LAT + col], s);
                atomicAdd(&g_sumsq[g * LAT + col], sq);
            }
        }
    }
}

__global__ __launch_bounds__(256, 2) void gemm2_mma_kernel() {
    float acc[4][4][4];
    const int z  = blockIdx.z;
    const int m0 = blockIdx.y * 128, n0 = blockIdx.x * 128;
    mma_mainloop<KPG, 32>(g_X2, g_W2s, m0, n0, z * 32, 32, acc);
    float* out = g_Zp + (size_t)z * NTOT * PROJ;
    const int lane = threadIdx.x & 31, w = threadIdx.x >> 5;
    const int wm = w & 1, wn = w >> 1;
#pragma unroll
    for (int mi = 0; mi < 4; mi++) {
        int row = m0 + wm * 64 + mi * 16 + (lane >> 2);
#pragma unroll
        for (int nf = 0; nf < 4; nf++) {
            int col = n0 + wn * 32 + nf * 8 + (lane & 3) * 2;
            *(float2*)(out + (size_t)row * PROJ + col) =
                make_float2(acc[mi][nf][0], acc[mi][nf][1]);
            *(float2*)(out + (size_t)(row + 8) * PROJ + col) =
                make_float2(acc[mi][nf][2], acc[mi][nf][3]);
        }
    }
}

// ---------------- BN finalize ---------------------------------------------------
__global__ void bnfinal_kernel(const float* __restrict__ gamma,
                               const float* __restrict__ beta) {
    int idx = blockIdx.x * 256 + threadIdx.x;
    int c = idx & (LAT - 1);
    const float inv = 1.0f / (float)BATCH;
    float mu  = g_sum[idx] * inv;
    float var = g_sumsq[idx] * inv - mu * mu;
    float a = gamma[c] * rsqrtf(var + 1e-5f);
    g_bna[idx] = a;
    g_bnc[idx] = beta[c] - mu * a;
}

// ---------------- fused BN + ReLU + [hi|lo] emit ------------------------------
__global__ void bnrelu_split_kernel() {
    size_t i = (size_t)blockIdx.x * 256 + threadIdx.x;
    int row = (int)(i >> 10);
    int g   = row >> 11;
    int c2  = (int)i & 1023;
    const float* Ac = g_bna + g * LAT;
    const float* Cc = g_bnc + g * LAT;
    float2 x = ((const float2*)g_X)[i];
    float2 y;
    y.x = fmaxf(fmaf(x.x, Ac[2 * c2 + 0], Cc[2 * c2 + 0]), 0.f);
    y.y = fmaxf(fmaf(x.y, Ac[2 * c2 + 1], Cc[2 * c2 + 1]), 0.f);
    split_pair(y, (__nv_bfloat162*)(g_X2 + (size_t)row * KPG), c2, 1024);
}

// ---------------- rownorm: sum split-K parts + bias, normalize, emit ----------
__global__ void rownorm_kernel(const float* __restrict__ b2) {
    int row  = blockIdx.x * 8 + (threadIdx.x >> 5);
    int lane = threadIdx.x & 31;
    const float4* p0 = (const float4*)(g_Zp + (size_t)row * PROJ);
    const float4* p1 = (const float4*)(g_Zp + (size_t)(NTOT + row) * PROJ);
    const float4* bb = (const float4*)b2;
    float4 v0, v1;
    {
        float4 a = p0[lane], b = p1[lane], c = bb[lane];
        v0 = make_float4(a.x + b.x + c.x, a.y + b.y + c.y,
                         a.z + b.z + c.z, a.w + b.w + c.w);
        float4 d = p0[lane + 32], e = p1[lane + 32], f = bb[lane + 32];
        v1 = make_float4(d.x + e.x + f.x, d.y + e.y + f.y,
                         d.z + e.z + f.z, d.w + e.w + f.w);
    }
    float ss = v0.x * v0.x + v0.y * v0.y + v0.z * v0.z + v0.w * v0.w
             + v1.x * v1.x + v1.y * v1.y + v1.z * v1.z + v1.w * v1.w;
#pragma unroll
    for (int off = 16; off; off >>= 1) ss += __shfl_xor_sync(0xffffffffu, ss, off);
    float s = 1.41421356237f / fmaxf(sqrtf(ss), 1e-8f);   // sqrt(1/TEMP)/||z||
    v0.x *= s; v0.y *= s; v0.z *= s; v0.w *= s;
    v1.x *= s; v1.y *= s; v1.z *= s; v1.w *= s;

    __nv_bfloat162* Z = (__nv_bfloat162*)(g_Zs + (size_t)row * KPZ);
    float vv[8] = {v0.x, v0.y, v0.z, v0.w, v1.x, v1.y, v1.z, v1.w};
    int cbase[2] = {lane * 2, (lane + 32) * 2};
#pragma unroll
    for (int h = 0; h < 2; h++) {
#pragma unroll
        for (int q = 0; q < 2; q++) {
            float2 xy = make_float2(vv[h * 4 + q * 2], vv[h * 4 + q * 2 + 1]);
            split_pair(xy, Z, cbase[h] + q, 128);
        }
    }
}

// ---------------- symmetric tensorized sim + online exp-sum ------------------
__global__ __launch_bounds__(256, 2) void sim_mma_kernel() {
    const int a = blockIdx.y, b = blockIdx.x;
    if (b < a) return;
    float acc[4][4][4];
    const int i0 = a * 128, j0 = b * 128;
    mma_mainloop<KPZ, 4>(g_Zs, g_Zs, i0, j0, 0, NCKZ, acc);

    const int lane = threadIdx.x & 31, w = threadIdx.x >> 5;
    const int wm = w & 1, wn = w >> 1;
    const int lr = lane >> 2;
    const int lc = (lane & 3) * 2;
    const bool offd = (a != b);

    float cs[4][2];
#pragma unroll
    for (int nf = 0; nf < 4; nf++) { cs[nf][0] = 0.f; cs[nf][1] = 0.f; }

#pragma unroll
    for (int mi = 0; mi < 4; mi++) {
        int row0 = i0 + wm * 64 + mi * 16 + lr;
        int row1 = row0 + 8;
        int p0 = (row0 < BATCH) ? row0 + BATCH : row0 - BATCH;
        int p1 = (row1 < BATCH) ? row1 + BATCH : row1 - BATCH;
        float rs0 = 0.f, rs1 = 0.f;
#pragma unroll
        for (int nf = 0; nf < 4; nf++) {
            int col = j0 + wn * 32 + nf * 8 + lc;
            float d00 = acc[mi][nf][0], d01 = acc[mi][nf][1];
            float d10 = acc[mi][nf][2], d11 = acc[mi][nf][3];
            if (col == p0)     { g_pos[row0] = d00; g_pos[col]     = d00; }
            if (col + 1 == p0) { g_pos[row0] = d01; g_pos[col + 1] = d01; }
            if (col == p1)     { g_pos[row1] = d10; g_pos[col]     = d10; }
            if (col + 1 == p1) { g_pos[row1] = d11; g_pos[col + 1] = d11; }
            float e00 = (col     != row0) ? fexp(d00 - 2.f) : 0.f;
            float e01 = (col + 1 != row0) ? fexp(d01 - 2.f) : 0.f;
            float e10 = (col     != row1) ? fexp(d10 - 2.f) : 0.f;
            float e11 = (col + 1 != row1) ? fexp(d11 - 2.f) : 0.f;
            rs0 += e00 + e01;
            rs1 += e10 + e11;
            if (offd) { cs[nf][0] += e00 + e10; cs[nf][1] += e01 + e11; }
        }
        rs0 += __shfl_xor_sync(0xffffffffu, rs0, 1);
        rs0 += __shfl_xor_sync(0xffffffffu, rs0, 2);
        rs1 += __shfl_xor_sync(0xffffffffu, rs1, 1);
        rs1 += __shfl_xor_sync(0xffffffffu, rs1, 2);
        if ((lane & 3) == 0) {
            atomicAdd(&g_S[row0], rs0);
            atomicAdd(&g_S[row1], rs1);
        }
    }
    if (offd) {
#pragma unroll
        for (int nf = 0; nf < 4; nf++) {
#pragma unroll
            for (int q = 0; q < 2; q++) {
                float v = cs[nf][q];
                v += __shfl_xor_sync(0xffffffffu, v, 4);
                v += __shfl_xor_sync(0xffffffffu, v, 8);
                v += __shfl_xor_sync(0xffffffffu, v, 16);
                if (lr == 0)
                    atomicAdd(&g_S[j0 + wn * 32 + nf * 8 + lc + q], v);
            }
        }
    }
}

// ---------------- final reduction --------------------------------------------
__global__ void loss_kernel(float* __restrict__ out) {
    __shared__ float red[256];
    int t = threadIdx.x;
    float s = 0.f;
    for (int i = t; i < NTOT; i += 256)
        s += 2.0f + logf(g_S[i]) - g_pos[i];
    red[t] = s;
    __syncthreads();
    for (int off = 128; off; off >>= 1) {
        if (t < off) red[t] += red[t + off];
        __syncthreads();
    }
    if (t == 0) out[0] = red[0] / (float)NTOT;
}

// ---------------- launch ------------------------------------------------------
extern "C" void kernel_launch(void* const* d_in, const int* in_sizes, int n_in,
                              void* d_out, int out_size) {
    const float* h_i   = (const float*)d_in[0];
    const float* h_j   = (const float*)d_in[1];
    const float* W1    = (const float*)d_in[2];
    const float* gamma = (const float*)d_in[3];
    const float* beta  = (const float*)d_in[4];
    const float* W2    = (const float*)d_in[5];
    const float* b2    = (const float*)d_in[6];
    float* out = (float*)d_out;

    const int GEMM_SMEM = 3 * 32768;   // 98304
    cudaFuncSetAttribute(gemm1_mma_kernel, cudaFuncAttributeMaxDynamicSharedMemorySize, GEMM_SMEM);
    cudaFuncSetAttribute(gemm2_mma_kernel, cudaFuncAttributeMaxDynamicSharedMemorySize, GEMM_SMEM);
    cudaFuncSetAttribute(sim_mma_kernel,   cudaFuncAttributeMaxDynamicSharedMemorySize, GEMM_SMEM);

    init_kernel<<<16, 256>>>();
    splitA_kernel<<<NTOT * 1024 / 256, 256>>>(h_i, h_j);
    splitW_kernel<<<(LAT + PROJ) * 1024 / 256, 256>>>(W1, W2);
    gemm1_mma_kernel<<<dim3(16, 32), 256, GEMM_SMEM>>>();
    bnfinal_kernel<<<16, 256>>>(gamma, beta);
    bnrelu_split_kernel<<<NTOT * 1024 / 256, 256>>>();
    gemm2_mma_kernel<<<dim3(2, 32, 2), 256, GEMM_SMEM>>>();
    rownorm_kernel<<<512, 256>>>(b2);
    sim_mma_kernel<<<dim3(32, 32), 256, GEMM_SMEM>>>();
    loss_kernel<<<1, 256>>>(out);
}

// round 7
// speedup vs baseline: 8.7785x; 1.5024x over previous
#include <cuda_runtime.h>
#include <cuda_bf16.h>
#include <math.h>
#include <stdint.h>

#define BATCH 2048
#define NTOT  4096
#define LAT   2048
#define PROJ  256
#define KPG   2048          // physical K for gemm operands: pure bf16 (1-term)
#define KPZ   512           // physical K for sim operand: [hi | lo]
#define NCK1  32            // gemm1 chunks (2048/64)
#define NCKZ  12            // sim chunks: 3-term (3*256/64)

// ---------------- device scratch (no runtime allocation allowed) -------------
__device__ __nv_bfloat16 g_A2[(size_t)NTOT * KPG];    // bf16(H)
__device__ __nv_bfloat16 g_B1s[(size_t)LAT * KPG];    // bf16(W1)
__device__ __nv_bfloat16 g_W2s[(size_t)PROJ * KPG];   // bf16(W2)
__device__ __nv_bfloat16 g_X2[(size_t)NTOT * KPG];    // bf16(relu(bn(X)))
__device__ __nv_bfloat16 g_Zs[(size_t)NTOT * KPZ];    // normalized Z [h | l]
__device__ float g_X[(size_t)NTOT * LAT];
__device__ float g_Zp[(size_t)2 * NTOT * PROJ];       // split-K partials
__device__ float g_sum[2 * LAT];
__device__ float g_sumsq[2 * LAT];
__device__ float g_bna[2 * LAT];
__device__ float g_bnc[2 * LAT];
__device__ float g_S[NTOT];
__device__ float g_pos[NTOT];

// ---------------- PTX helpers (baseline ISA only) ----------------------------
__device__ __forceinline__ uint32_t smem_u32(const void* p) {
    return (uint32_t)__cvta_generic_to_shared(p);
}
__device__ __forceinline__ void cp16(uint32_t dst, const void* src) {
    asm volatile("cp.async.cg.shared.global [%0], [%1], 16;" :: "r"(dst), "l"(src));
}
__device__ __forceinline__ void cp_commit() { asm volatile("cp.async.commit_group;"); }
__device__ __forceinline__ void cp_wait1()  { asm volatile("cp.async.wait_group 1;"); }
__device__ __forceinline__ void cp_wait0()  { asm volatile("cp.async.wait_group 0;"); }
__device__ __forceinline__ void ldsm_x4(uint32_t a, uint32_t& r0, uint32_t& r1,
                                        uint32_t& r2, uint32_t& r3) {
    asm volatile("ldmatrix.sync.aligned.m8n8.x4.shared.b16 {%0,%1,%2,%3}, [%4];"
                 : "=r"(r0), "=r"(r1), "=r"(r2), "=r"(r3) : "r"(a));
}
__device__ __forceinline__ void mma16816(float* c, const uint32_t* a, const uint32_t* b) {
    asm volatile("mma.sync.aligned.m16n8k16.row.col.f32.bf16.bf16.f32 "
                 "{%0,%1,%2,%3}, {%4,%5,%6,%7}, {%8,%9}, {%0,%1,%2,%3};"
                 : "+f"(c[0]), "+f"(c[1]), "+f"(c[2]), "+f"(c[3])
                 : "r"(a[0]), "r"(a[1]), "r"(a[2]), "r"(a[3]), "r"(b[0]), "r"(b[1]));
}

// FMA-only exp for y in ~[-4.1, 0.1]
__device__ __forceinline__ float fexp(float y) {
    float t = y * 1.4426950408889634f;
    float n = rintf(t);
    float f = t - n;
    float p =              1.5403530e-4f;
    p = fmaf(p, f, 1.3333558e-3f);
    p = fmaf(p, f, 9.6181291e-3f);
    p = fmaf(p, f, 5.5504109e-2f);
    p = fmaf(p, f, 2.4022651e-1f);
    p = fmaf(p, f, 6.9314718e-1f);
    p = fmaf(p, f, 1.0f);
    int e = ((int)n + 127) << 23;
    return p * __int_as_float(e);
}

// ---------------- init --------------------------------------------------------
__global__ void init_kernel() {
    int i = blockIdx.x * 256 + threadIdx.x;
    if (i < NTOT) g_S[i] = 0.f;
    if (i < 2 * LAT) { g_sum[i] = 0.f; g_sumsq[i] = 0.f; }
}

// ---------------- fp32 -> bf16 converts ---------------------------------------
__device__ __forceinline__ __nv_bfloat162 cvt2(const float2 v) {
    __nv_bfloat162 r; r.x = __float2bfloat16(v.x); r.y = __float2bfloat16(v.y);
    return r;
}

__global__ void cvtA_kernel(const float* __restrict__ hi_,
                            const float* __restrict__ hj_) {
    size_t i = (size_t)blockIdx.x * 256 + threadIdx.x;   // NTOT*1024 pairs
    float2 v = (i < (size_t)BATCH * 1024) ? ((const float2*)hi_)[i]
                                          : ((const float2*)hj_)[i - (size_t)BATCH * 1024];
    ((__nv_bfloat162*)g_A2)[i] = cvt2(v);
}

__global__ void cvtW_kernel(const float* __restrict__ W1,
                            const float* __restrict__ W2) {
    size_t i = (size_t)blockIdx.x * 256 + threadIdx.x;   // (LAT+PROJ)*1024 pairs
    const size_t n1 = (size_t)LAT * 1024;
    if (i < n1) ((__nv_bfloat162*)g_B1s)[i] = cvt2(((const float2*)W1)[i]);
    else        ((__nv_bfloat162*)g_W2s)[i - n1] = cvt2(((const float2*)W2)[i - n1]);
}

// ---------------- shared MMA mainloop (3-stage, single sync/iter) ------------
// CTA tile 128x128, BK=64 bf16 (128B rows, xor swizzle), 256 threads,
// 8 warps (2m x 4n), warp tile 64x32. K-chunk remap (used by sim 3-term):
//   A: mapA(c) = c < 2*KH ? c : c - 2*KH     B: mapB(c) = c < KH ? c : c - KH
template <int KPHYS, int KH>
__device__ __forceinline__ void mma_mainloop(const __nv_bfloat16* __restrict__ A,
                                             const __nv_bfloat16* __restrict__ B,
                                             int m0, int n0, int c0, int nck,
                                             float acc[4][4][4]) {
    extern __shared__ char smem[];
    const uint32_t sb = smem_u32(smem);
    const int tid  = threadIdx.x;
    const int lane = tid & 31;
    const int w    = tid >> 5;
    const int wm   = w & 1;
    const int wn   = w >> 1;

    auto load_tile = [&](int c) {
        const int cl = c0 + c;
        const int kA = ((cl < 2 * KH) ? cl : cl - 2 * KH) * 64;
        const int kB = ((cl < KH) ? cl : cl - KH) * 64;
        const uint32_t sA = sb + (uint32_t)(c % 3) * 32768u;
        const uint32_t sB = sA + 16384u;
#pragma unroll
        for (int i = 0; i < 4; i++) {
            int idx = i * 256 + tid;
            int row = idx >> 3, ch = idx & 7;
            uint32_t dst = (uint32_t)row * 128 + (uint32_t)((ch ^ (row & 7)) * 16);
            cp16(sA + dst, A + (size_t)(m0 + row) * KPHYS + kA + ch * 8);
            cp16(sB + dst, B + (size_t)(n0 + row) * KPHYS + kB + ch * 8);
        }
        cp_commit();
    };

#pragma unroll
    for (int i = 0; i < 4; i++)
#pragma unroll
        for (int j = 0; j < 4; j++)
#pragma unroll
            for (int q = 0; q < 4; q++) acc[i][j][q] = 0.f;

    const int rA   = wm * 64 + (lane & 15);
    const int khA  = lane >> 4;
    const int rB   = wn * 32 + ((lane >> 4) << 3) + (lane & 7);
    const int khB  = (lane >> 3) & 1;
    const int rlow = lane & 7;

    load_tile(0);
    load_tile(1);

    for (int c = 0; c < nck; c++) {
        if (c < nck - 1) cp_wait1(); else cp_wait0();
        __syncthreads();
        if (c + 2 < nck) load_tile(c + 2);
        const uint32_t sA = sb + (uint32_t)(c % 3) * 32768u;
        const uint32_t sB = sA + 16384u;
#pragma unroll
        for (int ks = 0; ks < 4; ks++) {
            uint32_t af[4][4], bf[4][2];
#pragma unroll
            for (int mi = 0; mi < 4; mi++) {
                uint32_t a = sA + (uint32_t)(rA + mi * 16) * 128
                           + (uint32_t)((((ks * 2) + khA) ^ rlow) * 16);
                ldsm_x4(a, af[mi][0], af[mi][1], af[mi][2], af[mi][3]);
            }
#pragma unroll
            for (int np = 0; np < 2; np++) {
                uint32_t r0, r1, r2, r3;
                uint32_t a = sB + (uint32_t)(rB + np * 16) * 128
                           + (uint32_t)((((ks * 2) + khB) ^ rlow) * 16);
                ldsm_x4(a, r0, r1, r2, r3);
                bf[np * 2 + 0][0] = r0; bf[np * 2 + 0][1] = r1;
                bf[np * 2 + 1][0] = r2; bf[np * 2 + 1][1] = r3;
            }
#pragma unroll
            for (int mi = 0; mi < 4; mi++)
#pragma unroll
                for (int nf = 0; nf < 4; nf++)
                    mma16816(acc[mi][nf], af[mi], bf[nf]);
        }
    }
}

// ---------------- GEMM1 (+fused BN column stats) ------------------------------
__global__ __launch_bounds__(256, 2) void gemm1_mma_kernel() {
    float acc[4][4][4];
    const int m0 = blockIdx.y * 128, n0 = blockIdx.x * 128;
    mma_mainloop<KPG, 32>(g_A2, g_B1s, m0, n0, 0, NCK1, acc);
    const int lane = threadIdx.x & 31, w = threadIdx.x >> 5;
    const int wm = w & 1, wn = w >> 1;
#pragma unroll
    for (int mi = 0; mi < 4; mi++) {
        int row = m0 + wm * 64 + mi * 16 + (lane >> 2);
#pragma unroll
        for (int nf = 0; nf < 4; nf++) {
            int col = n0 + wn * 32 + nf * 8 + (lane & 3) * 2;
            *(float2*)(g_X + (size_t)row * LAT + col) =
                make_float2(acc[mi][nf][0], acc[mi][nf][1]);
            *(float2*)(g_X + (size_t)(row + 8) * LAT + col) =
                make_float2(acc[mi][nf][2], acc[mi][nf][3]);
        }
    }
    // fused BN stats: per-column sum/sumsq over this tile's 128 rows
    const int g = m0 >> 11;
#pragma unroll
    for (int nf = 0; nf < 4; nf++) {
#pragma unroll
        for (int q = 0; q < 2; q++) {
            float s = 0.f, sq = 0.f;
#pragma unroll
            for (int mi = 0; mi < 4; mi++) {
                float v0 = acc[mi][nf][q];
                float v1 = acc[mi][nf][q + 2];
                s += v0 + v1;
                sq = fmaf(v0, v0, sq);
                sq = fmaf(v1, v1, sq);
            }
#pragma unroll
            for (int off = 4; off <= 16; off <<= 1) {
                s  += __shfl_xor_sync(0xffffffffu, s, off);
                sq += __shfl_xor_sync(0xffffffffu, sq, off);
            }
            if ((lane >> 2) == 0) {
                int col = n0 + wn * 32 + nf * 8 + (lane & 3) * 2 + q;
                atomicAdd(&g_sum[g * LAT + col], s);
                atomicAdd(&g_sumsq[g * LAT + col], sq);
            }
        }
    }
}

__global__ __launch_bounds__(256, 2) void gemm2_mma_kernel() {
    float acc[4][4][4];
    const int z  = blockIdx.z;
    const int m0 = blockIdx.y * 128, n0 = blockIdx.x * 128;
    mma_mainloop<KPG, 32>(g_X2, g_W2s, m0, n0, z * 16, 16, acc);
    float* out = g_Zp + (size_t)z * NTOT * PROJ;
    const int lane = threadIdx.x & 31, w = threadIdx.x >> 5;
    const int wm = w & 1, wn = w >> 1;
#pragma unroll
    for (int mi = 0; mi < 4; mi++) {
        int row = m0 + wm * 64 + mi * 16 + (lane >> 2);
#pragma unroll
        for (int nf = 0; nf < 4; nf++) {
            int col = n0 + wn * 32 + nf * 8 + (lane & 3) * 2;
            *(float2*)(out + (size_t)row * PROJ + col) =
                make_float2(acc[mi][nf][0], acc[mi][nf][1]);
            *(float2*)(out + (size_t)(row + 8) * PROJ + col) =
                make_float2(acc[mi][nf][2], acc[mi][nf][3]);
        }
    }
}

// ---------------- BN finalize ---------------------------------------------------
__global__ void bnfinal_kernel(const float* __restrict__ gamma,
                               const float* __restrict__ beta) {
    int idx = blockIdx.x * 256 + threadIdx.x;
    int c = idx & (LAT - 1);
    const float inv = 1.0f / (float)BATCH;
    float mu  = g_sum[idx] * inv;
    float var = g_sumsq[idx] * inv - mu * mu;
    float a = gamma[c] * rsqrtf(var + 1e-5f);
    g_bna[idx] = a;
    g_bnc[idx] = beta[c] - mu * a;
}

// ---------------- fused BN + ReLU + bf16 emit ---------------------------------
__global__ void bnrelu_kernel() {
    size_t i = (size_t)blockIdx.x * 256 + threadIdx.x;   // NTOT*1024 pairs
    int row = (int)(i >> 10);
    int g   = row >> 11;
    int c2  = (int)i & 1023;
    const float* Ac = g_bna + g * LAT;
    const float* Cc = g_bnc + g * LAT;
    float2 x = ((const float2*)g_X)[i];
    float2 y;
    y.x = fmaxf(fmaf(x.x, Ac[2 * c2 + 0], Cc[2 * c2 + 0]), 0.f);
    y.y = fmaxf(fmaf(x.y, Ac[2 * c2 + 1], Cc[2 * c2 + 1]), 0.f);
    ((__nv_bfloat162*)g_X2)[i] = cvt2(y);
}

// ---------------- rownorm: sum split-K parts + bias, normalize, emit [h|l] ----
__global__ void rownorm_kernel(const float* __restrict__ b2) {
    int row  = blockIdx.x * 8 + (threadIdx.x >> 5);
    int lane = threadIdx.x & 31;
    const float4* p0 = (const float4*)(g_Zp + (size_t)row * PROJ);
    const float4* p1 = (const float4*)(g_Zp + (size_t)(NTOT + row) * PROJ);
    const float4* bb = (const float4*)b2;
    float4 v0, v1;
    {
        float4 a = p0[lane], b = p1[lane], c = bb[lane];
        v0 = make_float4(a.x + b.x + c.x, a.y + b.y + c.y,
                         a.z + b.z + c.z, a.w + b.w + c.w);
        float4 d = p0[lane + 32], e = p1[lane + 32], f = bb[lane + 32];
        v1 = make_float4(d.x + e.x + f.x, d.y + e.y + f.y,
                         d.z + e.z + f.z, d.w + e.w + f.w);
    }
    float ss = v0.x * v0.x + v0.y * v0.y + v0.z * v0.z + v0.w * v0.w
             + v1.x * v1.x + v1.y * v1.y + v1.z * v1.z + v1.w * v1.w;
#pragma unroll
    for (int off = 16; off; off >>= 1) ss += __shfl_xor_sync(0xffffffffu, ss, off);
    float s = 1.41421356237f / fmaxf(sqrtf(ss), 1e-8f);   // sqrt(1/TEMP)/||z||
    v0.x *= s; v0.y *= s; v0.z *= s; v0.w *= s;
    v1.x *= s; v1.y *= s; v1.z *= s; v1.w *= s;

    __nv_bfloat162* Z = (__nv_bfloat162*)(g_Zs + (size_t)row * KPZ);
    float vv[8] = {v0.x, v0.y, v0.z, v0.w, v1.x, v1.y, v1.z, v1.w};
    int cbase[2] = {lane * 2, (lane + 32) * 2};
#pragma unroll
    for (int h = 0; h < 2; h++) {
#pragma unroll
        for (int q = 0; q < 2; q++) {
            float x = vv[h * 4 + q * 2], y = vv[h * 4 + q * 2 + 1];
            __nv_bfloat16 hx = __float2bfloat16(x), hy = __float2bfloat16(y);
            __nv_bfloat16 lx = __float2bfloat16(x - __bfloat162float(hx));
            __nv_bfloat16 ly = __float2bfloat16(y - __bfloat162float(hy));
            __nv_bfloat162 hi2; hi2.x = hx; hi2.y = hy;
            __nv_bfloat162 lo2; lo2.x = lx; lo2.y = ly;
            int c2 = cbase[h] + q;
            Z[c2] = hi2; Z[128 + c2] = lo2;
        }
    }
}

// ---------------- symmetric tensorized sim + online exp-sum ------------------
__global__ __launch_bounds__(256, 2) void sim_mma_kernel() {
    const int a = blockIdx.y, b = blockIdx.x;
    if (b < a) return;
    float acc[4][4][4];
    const int i0 = a * 128, j0 = b * 128;
    mma_mainloop<KPZ, 4>(g_Zs, g_Zs, i0, j0, 0, NCKZ, acc);

    const int lane = threadIdx.x & 31, w = threadIdx.x >> 5;
    const int wm = w & 1, wn = w >> 1;
    const int lr = lane >> 2;
    const int lc = (lane & 3) * 2;
    const bool offd = (a != b);

    float cs[4][2];
#pragma unroll
    for (int nf = 0; nf < 4; nf++) { cs[nf][0] = 0.f; cs[nf][1] = 0.f; }

#pragma unroll
    for (int mi = 0; mi < 4; mi++) {
        int row0 = i0 + wm * 64 + mi * 16 + lr;
        int row1 = row0 + 8;
        int p0 = (row0 < BATCH) ? row0 + BATCH : row0 - BATCH;
        int p1 = (row1 < BATCH) ? row1 + BATCH : row1 - BATCH;
        float rs0 = 0.f, rs1 = 0.f;
#pragma unroll
        for (int nf = 0; nf < 4; nf++) {
            int col = j0 + wn * 32 + nf * 8 + lc;
            float d00 = acc[mi][nf][0], d01 = acc[mi][nf][1];
            float d10 = acc[mi][nf][2], d11 = acc[mi][nf][3];
            if (col == p0)     { g_pos[row0] = d00; g_pos[col]     = d00; }
            if (col + 1 == p0) { g_pos[row0] = d01; g_pos[col + 1] = d01; }
            if (col == p1)     { g_pos[row1] = d10; g_pos[col]     = d10; }
            if (col + 1 == p1) { g_pos[row1] = d11; g_pos[col + 1] = d11; }
            float e00 = (col     != row0) ? fexp(d00 - 2.f) : 0.f;
            float e01 = (col + 1 != row0) ? fexp(d01 - 2.f) : 0.f;
            float e10 = (col     != row1) ? fexp(d10 - 2.f) : 0.f;
            float e11 = (col + 1 != row1) ? fexp(d11 - 2.f) : 0.f;
            rs0 += e00 + e01;
            rs1 += e10 + e11;
            if (offd) { cs[nf][0] += e00 + e10; cs[nf][1] += e01 + e11; }
        }
        rs0 += __shfl_xor_sync(0xffffffffu, rs0, 1);
        rs0 += __shfl_xor_sync(0xffffffffu, rs0, 2);
        rs1 += __shfl_xor_sync(0xffffffffu, rs1, 1);
        rs1 += __shfl_xor_sync(0xffffffffu, rs1, 2);
        if ((lane & 3) == 0) {
            atomicAdd(&g_S[row0], rs0);
            atomicAdd(&g_S[row1], rs1);
        }
    }
    if (offd) {
#pragma unroll
        for (int nf = 0; nf < 4; nf++) {
#pragma unroll
            for (int q = 0; q < 2; q++) {
                float v = cs[nf][q];
                v += __shfl_xor_sync(0xffffffffu, v, 4);
                v += __shfl_xor_sync(0xffffffffu, v, 8);
                v += __shfl_xor_sync(0xffffffffu, v, 16);
                if (lr == 0)
                    atomicAdd(&g_S[j0 + wn * 32 + nf * 8 + lc + q], v);
            }
        }
    }
}

// ---------------- final reduction --------------------------------------------
__global__ void loss_kernel(float* __restrict__ out) {
    __shared__ float red[256];
    int t = threadIdx.x;
    float s = 0.f;
    for (int i = t; i < NTOT; i += 256)
        s += 2.0f + logf(g_S[i]) - g_pos[i];
    red[t] = s;
    __syncthreads();
    for (int off = 128; off; off >>= 1) {
        if (t < off) red[t] += red[t + off];
        __syncthreads();
    }
    if (t == 0) out[0] = red[0] / (float)NTOT;
}

// ---------------- launch ------------------------------------------------------
extern "C" void kernel_launch(void* const* d_in, const int* in_sizes, int n_in,
                              void* d_out, int out_size) {
    const float* h_i   = (const float*)d_in[0];
    const float* h_j   = (const float*)d_in[1];
    const float* W1    = (const float*)d_in[2];
    const float* gamma = (const float*)d_in[3];
    const float* beta  = (const float*)d_in[4];
    const float* W2    = (const float*)d_in[5];
    const float* b2    = (const float*)d_in[6];
    float* out = (float*)d_out;

    const int GEMM_SMEM = 3 * 32768;   // 98304
    cudaFuncSetAttribute(gemm1_mma_kernel, cudaFuncAttributeMaxDynamicSharedMemorySize, GEMM_SMEM);
    cudaFuncSetAttribute(gemm2_mma_kernel, cudaFuncAttributeMaxDynamicSharedMemorySize, GEMM_SMEM);
    cudaFuncSetAttribute(sim_mma_kernel,   cudaFuncAttributeMaxDynamicSharedMemorySize, GEMM_SMEM);

    init_kernel<<<16, 256>>>();
    cvtA_kernel<<<NTOT * 1024 / 256, 256>>>(h_i, h_j);
    cvtW_kernel<<<(LAT + PROJ) * 1024 / 256, 256>>>(W1, W2);
    gemm1_mma_kernel<<<dim3(16, 32), 256, GEMM_SMEM>>>();
    bnfinal_kernel<<<16, 256>>>(gamma, beta);
    bnrelu_kernel<<<NTOT * 1024 / 256, 256>>>();
    gemm2_mma_kernel<<<dim3(2, 32, 2), 256, GEMM_SMEM>>>();
    rownorm_kernel<<<512, 256>>>(b2);
    sim_mma_kernel<<<dim3(32, 32), 256, GEMM_SMEM>>>();
    loss_kernel<<<1, 256>>>(out);
}

// round 8
// speedup vs baseline: 9.7206x; 1.1073x over previous
#include <cuda_runtime.h>
#include <cuda_bf16.h>
#include <math.h>
#include <stdint.h>

#define BATCH 2048
#define NTOT  4096
#define LAT   2048
#define PROJ  256
#define KPG   2048          // physical K for gemm operands (pure bf16)
#define KPZ   256           // physical K for sim operand (pure bf16)
#define NCK1  32            // gemm1 chunks (2048/64)
#define NCKZ  4             // sim chunks (256/64)

// ---------------- device scratch (no runtime allocation allowed) -------------
__device__ __nv_bfloat16 g_A2[(size_t)NTOT * KPG];    // bf16(H)
__device__ __nv_bfloat16 g_B1s[(size_t)LAT * KPG];    // bf16(W1)
__device__ __nv_bfloat16 g_W2s[(size_t)PROJ * KPG];   // bf16(W2)
__device__ __nv_bfloat16 g_X2[(size_t)NTOT * KPG];    // bf16(relu(bn(X)))
__device__ __nv_bfloat16 g_Zs[(size_t)NTOT * KPZ];    // bf16(normalized Z)
__device__ float g_X[(size_t)NTOT * LAT];
__device__ float g_Zp[(size_t)2 * NTOT * PROJ];       // split-K partials
__device__ float g_sum[2 * LAT];
__device__ float g_sumsq[2 * LAT];
__device__ float g_bna[2 * LAT];
__device__ float g_bnc[2 * LAT];
__device__ float g_S[NTOT];
__device__ float g_pos[NTOT];

// ---------------- PTX helpers (baseline ISA only) ----------------------------
__device__ __forceinline__ uint32_t smem_u32(const void* p) {
    return (uint32_t)__cvta_generic_to_shared(p);
}
__device__ __forceinline__ void cp16(uint32_t dst, const void* src) {
    asm volatile("cp.async.cg.shared.global [%0], [%1], 16;" :: "r"(dst), "l"(src));
}
__device__ __forceinline__ void cp_commit() { asm volatile("cp.async.commit_group;"); }
__device__ __forceinline__ void cp_wait1()  { asm volatile("cp.async.wait_group 1;"); }
__device__ __forceinline__ void cp_wait0()  { asm volatile("cp.async.wait_group 0;"); }
__device__ __forceinline__ void ldsm_x4(uint32_t a, uint32_t& r0, uint32_t& r1,
                                        uint32_t& r2, uint32_t& r3) {
    asm volatile("ldmatrix.sync.aligned.m8n8.x4.shared.b16 {%0,%1,%2,%3}, [%4];"
                 : "=r"(r0), "=r"(r1), "=r"(r2), "=r"(r3) : "r"(a));
}
__device__ __forceinline__ void mma16816(float* c, const uint32_t* a, const uint32_t* b) {
    asm volatile("mma.sync.aligned.m16n8k16.row.col.f32.bf16.bf16.f32 "
                 "{%0,%1,%2,%3}, {%4,%5,%6,%7}, {%8,%9}, {%0,%1,%2,%3};"
                 : "+f"(c[0]), "+f"(c[1]), "+f"(c[2]), "+f"(c[3])
                 : "r"(a[0]), "r"(a[1]), "r"(a[2]), "r"(a[3]), "r"(b[0]), "r"(b[1]));
}

// FMA-only exp for y in ~[-4.1, 0.1]
__device__ __forceinline__ float fexp(float y) {
    float t = y * 1.4426950408889634f;
    float n = rintf(t);
    float f = t - n;
    float p =              1.5403530e-4f;
    p = fmaf(p, f, 1.3333558e-3f);
    p = fmaf(p, f, 9.6181291e-3f);
    p = fmaf(p, f, 5.5504109e-2f);
    p = fmaf(p, f, 2.4022651e-1f);
    p = fmaf(p, f, 6.9314718e-1f);
    p = fmaf(p, f, 1.0f);
    int e = ((int)n + 127) << 23;
    return p * __int_as_float(e);
}

// ---------------- fp32 -> bf16 converts (init folded into cvtA) --------------
__device__ __forceinline__ __nv_bfloat162 cvt2(const float2 v) {
    __nv_bfloat162 r; r.x = __float2bfloat16(v.x); r.y = __float2bfloat16(v.y);
    return r;
}

__global__ void cvtA_kernel(const float* __restrict__ hi_,
                            const float* __restrict__ hj_) {
    size_t i = (size_t)blockIdx.x * 256 + threadIdx.x;   // NTOT*1024 pairs
    if (i < NTOT) g_S[i] = 0.f;
    if (i < 2 * LAT) { g_sum[i] = 0.f; g_sumsq[i] = 0.f; }
    float2 v = (i < (size_t)BATCH * 1024) ? ((const float2*)hi_)[i]
                                          : ((const float2*)hj_)[i - (size_t)BATCH * 1024];
    ((__nv_bfloat162*)g_A2)[i] = cvt2(v);
}

__global__ void cvtW_kernel(const float* __restrict__ W1,
                            const float* __restrict__ W2) {
    size_t i = (size_t)blockIdx.x * 256 + threadIdx.x;   // (LAT+PROJ)*1024 pairs
    const size_t n1 = (size_t)LAT * 1024;
    if (i < n1) ((__nv_bfloat162*)g_B1s)[i] = cvt2(((const float2*)W1)[i]);
    else        ((__nv_bfloat162*)g_W2s)[i - n1] = cvt2(((const float2*)W2)[i - n1]);
}

// ---------------- 8-warp MMA mainloop (gemm2 + sim) ---------------------------
// CTA tile 128x128, BK=64, 256 threads, warp tile 64x32.
template <int KPHYS, int KH>
__device__ __forceinline__ void mma_mainloop(const __nv_bfloat16* __restrict__ A,
                                             const __nv_bfloat16* __restrict__ B,
                                             int m0, int n0, int c0, int nck,
                                             float acc[4][4][4]) {
    extern __shared__ char smem[];
    const uint32_t sb = smem_u32(smem);
    const int tid  = threadIdx.x;
    const int lane = tid & 31;
    const int w    = tid >> 5;
    const int wm   = w & 1;
    const int wn   = w >> 1;

    auto load_tile = [&](int c) {
        const int cl = c0 + c;
        const int kA = ((cl < 2 * KH) ? cl : cl - 2 * KH) * 64;
        const int kB = ((cl < KH) ? cl : cl - KH) * 64;
        const uint32_t sA = sb + (uint32_t)(c % 3) * 32768u;
        const uint32_t sB = sA + 16384u;
#pragma unroll
        for (int i = 0; i < 4; i++) {
            int idx = i * 256 + tid;
            int row = idx >> 3, ch = idx & 7;
            uint32_t dst = (uint32_t)row * 128 + (uint32_t)((ch ^ (row & 7)) * 16);
            cp16(sA + dst, A + (size_t)(m0 + row) * KPHYS + kA + ch * 8);
            cp16(sB + dst, B + (size_t)(n0 + row) * KPHYS + kB + ch * 8);
        }
        cp_commit();
    };

#pragma unroll
    for (int i = 0; i < 4; i++)
#pragma unroll
        for (int j = 0; j < 4; j++)
#pragma unroll
            for (int q = 0; q < 4; q++) acc[i][j][q] = 0.f;

    const int rA   = wm * 64 + (lane & 15);
    const int khA  = lane >> 4;
    const int rB   = wn * 32 + ((lane >> 4) << 3) + (lane & 7);
    const int khB  = (lane >> 3) & 1;
    const int rlow = lane & 7;

    load_tile(0);
    load_tile(1);

    for (int c = 0; c < nck; c++) {
        if (c < nck - 1) cp_wait1(); else cp_wait0();
        __syncthreads();
        if (c + 2 < nck) load_tile(c + 2);
        const uint32_t sA = sb + (uint32_t)(c % 3) * 32768u;
        const uint32_t sB = sA + 16384u;
#pragma unroll
        for (int ks = 0; ks < 4; ks++) {
            uint32_t af[4][4], bf[4][2];
#pragma unroll
            for (int mi = 0; mi < 4; mi++) {
                uint32_t a = sA + (uint32_t)(rA + mi * 16) * 128
                           + (uint32_t)((((ks * 2) + khA) ^ rlow) * 16);
                ldsm_x4(a, af[mi][0], af[mi][1], af[mi][2], af[mi][3]);
            }
#pragma unroll
            for (int np = 0; np < 2; np++) {
                uint32_t r0, r1, r2, r3;
                uint32_t a = sB + (uint32_t)(rB + np * 16) * 128
                           + (uint32_t)((((ks * 2) + khB) ^ rlow) * 16);
                ldsm_x4(a, r0, r1, r2, r3);
                bf[np * 2 + 0][0] = r0; bf[np * 2 + 0][1] = r1;
                bf[np * 2 + 1][0] = r2; bf[np * 2 + 1][1] = r3;
            }
#pragma unroll
            for (int mi = 0; mi < 4; mi++)
#pragma unroll
                for (int nf = 0; nf < 4; nf++)
                    mma16816(acc[mi][nf], af[mi], bf[nf]);
        }
    }
}

// ---------------- GEMM1: 4-warp CTA, warp tile 64x64 (+fused BN stats) -------
__global__ __launch_bounds__(128, 2) void gemm1_mma_kernel() {
    extern __shared__ char smem[];
    const uint32_t sb = smem_u32(smem);
    const int tid  = threadIdx.x;
    const int lane = tid & 31;
    const int w    = tid >> 5;
    const int wm   = w & 1;        // 0..1: 64-row slab
    const int wn   = w >> 1;       // 0..1: 64-col slab
    const int m0 = blockIdx.y * 128, n0 = blockIdx.x * 128;

    auto load_tile = [&](int c) {
        const int k0 = c * 64;
        const uint32_t sA = sb + (uint32_t)(c % 3) * 32768u;
        const uint32_t sB = sA + 16384u;
#pragma unroll
        for (int i = 0; i < 8; i++) {
            int idx = i * 128 + tid;          // 0..1023
            int row = idx >> 3, ch = idx & 7;
            uint32_t dst = (uint32_t)row * 128 + (uint32_t)((ch ^ (row & 7)) * 16);
            cp16(sA + dst, g_A2 + (size_t)(m0 + row) * KPG + k0 + ch * 8);
            cp16(sB + dst, g_B1s + (size_t)(n0 + row) * KPG + k0 + ch * 8);
        }
        cp_commit();
    };

    float acc[4][8][4];
#pragma unroll
    for (int i = 0; i < 4; i++)
#pragma unroll
        for (int j = 0; j < 8; j++)
#pragma unroll
            for (int q = 0; q < 4; q++) acc[i][j][q] = 0.f;

    const int rA   = wm * 64 + (lane & 15);
    const int khA  = lane >> 4;
    const int rB   = wn * 64 + ((lane >> 4) << 3) + (lane & 7);
    const int khB  = (lane >> 3) & 1;
    const int rlow = lane & 7;

    load_tile(0);
    load_tile(1);

    for (int c = 0; c < NCK1; c++) {
        if (c < NCK1 - 1) cp_wait1(); else cp_wait0();
        __syncthreads();
        if (c + 2 < NCK1) load_tile(c + 2);
        const uint32_t sA = sb + (uint32_t)(c % 3) * 32768u;
        const uint32_t sB = sA + 16384u;
#pragma unroll
        for (int ks = 0; ks < 4; ks++) {
            uint32_t af[4][4], bf[8][2];
#pragma unroll
            for (int mi = 0; mi < 4; mi++) {
                uint32_t a = sA + (uint32_t)(rA + mi * 16) * 128
                           + (uint32_t)((((ks * 2) + khA) ^ rlow) * 16);
                ldsm_x4(a, af[mi][0], af[mi][1], af[mi][2], af[mi][3]);
            }
#pragma unroll
            for (int np = 0; np < 4; np++) {
                uint32_t r0, r1, r2, r3;
                uint32_t a = sB + (uint32_t)(rB + np * 16) * 128
                           + (uint32_t)((((ks * 2) + khB) ^ rlow) * 16);
                ldsm_x4(a, r0, r1, r2, r3);
                bf[np * 2 + 0][0] = r0; bf[np * 2 + 0][1] = r1;
                bf[np * 2 + 1][0] = r2; bf[np * 2 + 1][1] = r3;
            }
#pragma unroll
            for (int mi = 0; mi < 4; mi++)
#pragma unroll
                for (int nf = 0; nf < 8; nf++)
                    mma16816(acc[mi][nf], af[mi], bf[nf]);
        }
    }

    // epilogue: write fp32 X + fused BN column stats
#pragma unroll
    for (int mi = 0; mi < 4; mi++) {
        int row = m0 + wm * 64 + mi * 16 + (lane >> 2);
#pragma unroll
        for (int nf = 0; nf < 8; nf++) {
            int col = n0 + wn * 64 + nf * 8 + (lane & 3) * 2;
            *(float2*)(g_X + (size_t)row * LAT + col) =
                make_float2(acc[mi][nf][0], acc[mi][nf][1]);
            *(float2*)(g_X + (size_t)(row + 8) * LAT + col) =
                make_float2(acc[mi][nf][2], acc[mi][nf][3]);
        }
    }
    const int g = m0 >> 11;
#pragma unroll
    for (int nf = 0; nf < 8; nf++) {
#pragma unroll
        for (int q = 0; q < 2; q++) {
            float s = 0.f, sq = 0.f;
#pragma unroll
            for (int mi = 0; mi < 4; mi++) {
                float v0 = acc[mi][nf][q];
                float v1 = acc[mi][nf][q + 2];
                s += v0 + v1;
                sq = fmaf(v0, v0, sq);
                sq = fmaf(v1, v1, sq);
            }
#pragma unroll
            for (int off = 4; off <= 16; off <<= 1) {
                s  += __shfl_xor_sync(0xffffffffu, s, off);
                sq += __shfl_xor_sync(0xffffffffu, sq, off);
            }
            if ((lane >> 2) == 0) {
                int col = n0 + wn * 64 + nf * 8 + (lane & 3) * 2 + q;
                atomicAdd(&g_sum[g * LAT + col], s);
                atomicAdd(&g_sumsq[g * LAT + col], sq);
            }
        }
    }
}

// ---------------- GEMM2 (8-warp core, split-K=2) -------------------------------
__global__ __launch_bounds__(256, 2) void gemm2_mma_kernel() {
    float acc[4][4][4];
    const int z  = blockIdx.z;
    const int m0 = blockIdx.y * 128, n0 = blockIdx.x * 128;
    mma_mainloop<KPG, 32>(g_X2, g_W2s, m0, n0, z * 16, 16, acc);
    float* out = g_Zp + (size_t)z * NTOT * PROJ;
    const int lane = threadIdx.x & 31, w = threadIdx.x >> 5;
    const int wm = w & 1, wn = w >> 1;
#pragma unroll
    for (int mi = 0; mi < 4; mi++) {
        int row = m0 + wm * 64 + mi * 16 + (lane >> 2);
#pragma unroll
        for (int nf = 0; nf < 4; nf++) {
            int col = n0 + wn * 32 + nf * 8 + (lane & 3) * 2;
            *(float2*)(out + (size_t)row * PROJ + col) =
                make_float2(acc[mi][nf][0], acc[mi][nf][1]);
            *(float2*)(out + (size_t)(row + 8) * PROJ + col) =
                make_float2(acc[mi][nf][2], acc[mi][nf][3]);
        }
    }
}

// ---------------- BN finalize ---------------------------------------------------
__global__ void bnfinal_kernel(const float* __restrict__ gamma,
                               const float* __restrict__ beta) {
    int idx = blockIdx.x * 256 + threadIdx.x;
    int c = idx & (LAT - 1);
    const float inv = 1.0f / (float)BATCH;
    float mu  = g_sum[idx] * inv;
    float var = g_sumsq[idx] * inv - mu * mu;
    float a = gamma[c] * rsqrtf(var + 1e-5f);
    g_bna[idx] = a;
    g_bnc[idx] = beta[c] - mu * a;
}

// ---------------- fused BN + ReLU + bf16 emit ---------------------------------
__global__ void bnrelu_kernel() {
    size_t i = (size_t)blockIdx.x * 256 + threadIdx.x;   // NTOT*1024 pairs
    int row = (int)(i >> 10);
    int g   = row >> 11;
    int c2  = (int)i & 1023;
    const float* Ac = g_bna + g * LAT;
    const float* Cc = g_bnc + g * LAT;
    float2 x = ((const float2*)g_X)[i];
    float2 y;
    y.x = fmaxf(fmaf(x.x, Ac[2 * c2 + 0], Cc[2 * c2 + 0]), 0.f);
    y.y = fmaxf(fmaf(x.y, Ac[2 * c2 + 1], Cc[2 * c2 + 1]), 0.f);
    ((__nv_bfloat162*)g_X2)[i] = cvt2(y);
}

// ---------------- rownorm: sum split-K parts + bias, normalize, emit bf16 -----
__global__ void rownorm_kernel(const float* __restrict__ b2) {
    int row  = blockIdx.x * 8 + (threadIdx.x >> 5);
    int lane = threadIdx.x & 31;
    const float4* p0 = (const float4*)(g_Zp + (size_t)row * PROJ);
    const float4* p1 = (const float4*)(g_Zp + (size_t)(NTOT + row) * PROJ);
    const float4* bb = (const float4*)b2;
    float4 v0, v1;
    {
        float4 a = p0[lane], b = p1[lane], c = bb[lane];
        v0 = make_float4(a.x + b.x + c.x, a.y + b.y + c.y,
                         a.z + b.z + c.z, a.w + b.w + c.w);
        float4 d = p0[lane + 32], e = p1[lane + 32], f = bb[lane + 32];
        v1 = make_float4(d.x + e.x + f.x, d.y + e.y + f.y,
                         d.z + e.z + f.z, d.w + e.w + f.w);
    }
    float ss = v0.x * v0.x + v0.y * v0.y + v0.z * v0.z + v0.w * v0.w
             + v1.x * v1.x + v1.y * v1.y + v1.z * v1.z + v1.w * v1.w;
#pragma unroll
    for (int off = 16; off; off >>= 1) ss += __shfl_xor_sync(0xffffffffu, ss, off);
    float s = 1.41421356237f / fmaxf(sqrtf(ss), 1e-8f);   // sqrt(1/TEMP)/||z||
    v0.x *= s; v0.y *= s; v0.z *= s; v0.w *= s;
    v1.x *= s; v1.y *= s; v1.z *= s; v1.w *= s;

    __nv_bfloat162* Z = (__nv_bfloat162*)(g_Zs + (size_t)row * KPZ);
    Z[lane * 2 + 0]        = cvt2(make_float2(v0.x, v0.y));
    Z[lane * 2 + 1]        = cvt2(make_float2(v0.z, v0.w));
    Z[(lane + 32) * 2 + 0] = cvt2(make_float2(v1.x, v1.y));
    Z[(lane + 32) * 2 + 1] = cvt2(make_float2(v1.z, v1.w));
}

// ---------------- symmetric tensorized sim + online exp-sum ------------------
__global__ __launch_bounds__(256, 2) void sim_mma_kernel() {
    const int a = blockIdx.y, b = blockIdx.x;
    if (b < a) return;
    float acc[4][4][4];
    const int i0 = a * 128, j0 = b * 128;
    mma_mainloop<KPZ, 4>(g_Zs, g_Zs, i0, j0, 0, NCKZ, acc);

    const int lane = threadIdx.x & 31, w = threadIdx.x >> 5;
    const int wm = w & 1, wn = w >> 1;
    const int lr = lane >> 2;
    const int lc = (lane & 3) * 2;
    const bool offd = (a != b);

    float cs[4][2];
#pragma unroll
    for (int nf = 0; nf < 4; nf++) { cs[nf][0] = 0.f; cs[nf][1] = 0.f; }

#pragma unroll
    for (int mi = 0; mi < 4; mi++) {
        int row0 = i0 + wm * 64 + mi * 16 + lr;
        int row1 = row0 + 8;
        int p0 = (row0 < BATCH) ? row0 + BATCH : row0 - BATCH;
        int p1 = (row1 < BATCH) ? row1 + BATCH : row1 - BATCH;
        float rs0 = 0.f, rs1 = 0.f;
#pragma unroll
        for (int nf = 0; nf < 4; nf++) {
            int col = j0 + wn * 32 + nf * 8 + lc;
            float d00 = acc[mi][nf][0], d01 = acc[mi][nf][1];
            float d10 = acc[mi][nf][2], d11 = acc[mi][nf][3];
            if (col == p0)     { g_pos[row0] = d00; g_pos[col]     = d00; }
            if (col + 1 == p0) { g_pos[row0] = d01; g_pos[col + 1] = d01; }
            if (col == p1)     { g_pos[row1] = d10; g_pos[col]     = d10; }
            if (col + 1 == p1) { g_pos[row1] = d11; g_pos[col + 1] = d11; }
            float e00 = (col     != row0) ? fexp(d00 - 2.f) : 0.f;
            float e01 = (col + 1 != row0) ? fexp(d01 - 2.f) : 0.f;
            float e10 = (col     != row1) ? fexp(d10 - 2.f) : 0.f;
            float e11 = (col + 1 != row1) ? fexp(d11 - 2.f) : 0.f;
            rs0 += e00 + e01;
            rs1 += e10 + e11;
            if (offd) { cs[nf][0] += e00 + e10; cs[nf][1] += e01 + e11; }
        }
        rs0 += __shfl_xor_sync(0xffffffffu, rs0, 1);
        rs0 += __shfl_xor_sync(0xffffffffu, rs0, 2);
        rs1 += __shfl_xor_sync(0xffffffffu, rs1, 1);
        rs1 += __shfl_xor_sync(0xffffffffu, rs1, 2);
        if ((lane & 3) == 0) {
            atomicAdd(&g_S[row0], rs0);
            atomicAdd(&g_S[row1], rs1);
        }
    }
    if (offd) {
#pragma unroll
        for (int nf = 0; nf < 4; nf++) {
#pragma unroll
            for (int q = 0; q < 2; q++) {
                float v = cs[nf][q];
                v += __shfl_xor_sync(0xffffffffu, v, 4);
                v += __shfl_xor_sync(0xffffffffu, v, 8);
                v += __shfl_xor_sync(0xffffffffu, v, 16);
                if (lr == 0)
                    atomicAdd(&g_S[j0 + wn * 32 + nf * 8 + lc + q], v);
            }
        }
    }
}

// ---------------- final reduction --------------------------------------------
__global__ void loss_kernel(float* __restrict__ out) {
    __shared__ float red[256];
    int t = threadIdx.x;
    float s = 0.f;
    for (int i = t; i < NTOT; i += 256)
        s += 2.0f + logf(g_S[i]) - g_pos[i];
    red[t] = s;
    __syncthreads();
    for (int off = 128; off; off >>= 1) {
        if (t < off) red[t] += red[t + off];
        __syncthreads();
    }
    if (t == 0) out[0] = red[0] / (float)NTOT;
}

// ---------------- launch ------------------------------------------------------
extern "C" void kernel_launch(void* const* d_in, const int* in_sizes, int n_in,
                              void* d_out, int out_size) {
    const float* h_i   = (const float*)d_in[0];
    const float* h_j   = (const float*)d_in[1];
    const float* W1    = (const float*)d_in[2];
    const float* gamma = (const float*)d_in[3];
    const float* beta  = (const float*)d_in[4];
    const float* W2    = (const float*)d_in[5];
    const float* b2    = (const float*)d_in[6];
    float* out = (float*)d_out;

    const int GEMM_SMEM = 3 * 32768;   // 98304
    cudaFuncSetAttribute(gemm1_mma_kernel, cudaFuncAttributeMaxDynamicSharedMemorySize, GEMM_SMEM);
    cudaFuncSetAttribute(gemm2_mma_kernel, cudaFuncAttributeMaxDynamicSharedMemorySize, GEMM_SMEM);
    cudaFuncSetAttribute(sim_mma_kernel,   cudaFuncAttributeMaxDynamicSharedMemorySize, GEMM_SMEM);

    cvtA_kernel<<<NTOT * 1024 / 256, 256>>>(h_i, h_j);
    cvtW_kernel<<<(LAT + PROJ) * 1024 / 256, 256>>>(W1, W2);
    gemm1_mma_kernel<<<dim3(16, 32), 128, GEMM_SMEM>>>();
    bnfinal_kernel<<<16, 256>>>(gamma, beta);
    bnrelu_kernel<<<NTOT * 1024 / 256, 256>>>();
    gemm2_mma_kernel<<<dim3(2, 32, 2), 256, GEMM_SMEM>>>();
    rownorm_kernel<<<512, 256>>>(b2);
    sim_mma_kernel<<<dim3(32, 32), 256, GEMM_SMEM>>>();
    loss_kernel<<<1, 256>>>(out);
}